// round 12
// baseline (speedup 1.0000x reference)
#include <cuda_runtime.h>
#include <cuda_bf16.h>
#include <cuda_fp16.h>
#include <cstdint>

#define BB 256
#define MM 80
#define TT 1000
#define HH 128
#define GG 384
#define TPAD 1024

// ---------------- device scratch ----------------
__device__ float g_gx[(size_t)BB * TT * GG];                // 393 MB
__device__ __nv_bfloat16 g_xhi[(size_t)BB * TPAD * MM];     // 42 MB
__device__ __nv_bfloat16 g_xlo[(size_t)BB * TPAD * MM];     // 42 MB

// ---------------- helpers ----------------
__device__ __forceinline__ float fast_sigmoid(float x) {
    float e = __expf(-x);
    return __fdividef(1.0f, 1.0f + e);
}
__device__ __forceinline__ float fast_tanh(float x) {
    float ax = fabsf(x);
    float e = __expf(-2.0f * ax);
    float t = __fdividef(1.0f - e, 1.0f + e);
    return copysignf(t, x);
}
__device__ __forceinline__ void cp16(uint32_t saddr, const void* g) {
    asm volatile("cp.async.cg.shared.global [%0], [%1], 16;" :: "r"(saddr), "l"(g));
}
__device__ __forceinline__ void cp_commit() { asm volatile("cp.async.commit_group;" ::: "memory"); }
__device__ __forceinline__ void cp_wait0()  { asm volatile("cp.async.wait_group 0;" ::: "memory"); }
__device__ __forceinline__ uint32_t smem_u32(const void* p) {
    uint32_t a;
    asm("{ .reg .u64 t; cvta.to.shared.u64 t, %1; cvt.u32.u64 %0, t; }" : "=r"(a) : "l"(p));
    return a;
}
#define BAR_SYNC(id, cnt)   asm volatile("bar.sync %0, %1;"   :: "r"(id), "r"(cnt) : "memory")
#define BAR_ARRIVE(id, cnt) asm volatile("bar.arrive %0, %1;" :: "r"(id), "r"(cnt) : "memory")
// bf16 mma (gx kernel)
__device__ __forceinline__ void mma16816(float* c, uint32_t a0, uint32_t a1,
                                         uint32_t a2, uint32_t a3,
                                         uint32_t b0, uint32_t b1) {
    asm("mma.sync.aligned.m16n8k16.row.col.f32.bf16.bf16.f32 "
        "{%0,%1,%2,%3}, {%4,%5,%6,%7}, {%8,%9}, {%0,%1,%2,%3};"
        : "+f"(c[0]), "+f"(c[1]), "+f"(c[2]), "+f"(c[3])
        : "r"(a0), "r"(a1), "r"(a2), "r"(a3), "r"(b0), "r"(b1));
}
// fp16 mma (gru kernel)
__device__ __forceinline__ void mma16816h(float* c, uint32_t a0, uint32_t a1,
                                          uint32_t a2, uint32_t a3,
                                          uint32_t b0, uint32_t b1) {
    asm("mma.sync.aligned.m16n8k16.row.col.f32.f16.f16.f32 "
        "{%0,%1,%2,%3}, {%4,%5,%6,%7}, {%8,%9}, {%0,%1,%2,%3};"
        : "+f"(c[0]), "+f"(c[1]), "+f"(c[2]), "+f"(c[3])
        : "r"(a0), "r"(a1), "r"(a2), "r"(a3), "r"(b0), "r"(b1));
}
__device__ __forceinline__ uint32_t f16_pack(float a, float b) {
    __half2 p = __floats2half2_rn(a, b);
    return reinterpret_cast<uint32_t&>(p);
}
__device__ __forceinline__ uint32_t f16_lo_pack(float a, float b) {
    float ra = a - __half2float(__float2half_rn(a));
    float rb = b - __half2float(__float2half_rn(b));
    return f16_pack(ra, rb);
}

// ================= prep: transpose + bf16 split =================
#define PREP_THREADS 256
__global__ __launch_bounds__(PREP_THREADS)
void prep_kernel(const float* __restrict__ x)
{
    __shared__ float xs[MM][129];
    const int b = blockIdx.y, t0 = blockIdx.x * 128;
    const int tid = threadIdx.x;

    for (int idx = tid; idx < MM * 128; idx += PREP_THREADS) {
        int m = idx >> 7, j = idx & 127;
        int t = t0 + j;
        xs[m][j] = (t < TT) ? x[((size_t)b * MM + m) * TT + t] : 0.0f;
    }
    __syncthreads();

    for (int idx = tid; idx < 128 * 10; idx += PREP_THREADS) {
        int j = idx / 10, mv = idx % 10;
        int m0 = mv * 8;
        __align__(16) __nv_bfloat16 hi[8];
        __align__(16) __nv_bfloat16 lo[8];
        #pragma unroll
        for (int u = 0; u < 8; u++) {
            float v = xs[m0 + u][j];
            __nv_bfloat16 h = __float2bfloat16(v);
            hi[u] = h;
            lo[u] = __float2bfloat16(v - __bfloat162float(h));
        }
        size_t off = ((size_t)b * TPAD + t0 + j) * MM + m0;
        *(uint4*)(g_xhi + off) = *(const uint4*)hi;
        *(uint4*)(g_xlo + off) = *(const uint4*)lo;
    }
}

// ================= gx via mma.sync HMMA (split-bf16, 3 terms) =================
#define GXT 256
#define A_PITCH 88
#define W_PITCH 84
#define SM_AHI 0
#define SM_ALO (128 * A_PITCH * 2)
#define SM_WHI (SM_ALO + 128 * A_PITCH * 2)
#define SM_WLO (SM_WHI + 192 * W_PITCH * 2)
#define GX_SMEM (SM_WLO + 192 * W_PITCH * 2)

__device__ __forceinline__ uint32_t lds_pair(const char* base, int row, int col, int pitch) {
    return *(const uint32_t*)(base + (size_t)(row * pitch + col) * 2);
}

__global__ __launch_bounds__(GXT)
void gx_hmma_kernel(const float* __restrict__ W_ih)
{
    extern __shared__ char sm[];
    const int tid = threadIdx.x;
    const int lane = tid & 31;
    const int w = tid >> 5;
    const int grp = lane >> 2;
    const int q = lane & 3;
    const int tt = blockIdx.x >> 1;
    const int ghalf = blockIdx.x & 1;
    const int gbase = ghalf * 192;
    const int b = blockIdx.y;
    const uint32_t sb = smem_u32(sm);

    for (int i = tid; i < 2560; i += GXT) {
        int split = i / 1280;
        int rem = i - split * 1280;
        int row = rem / 10, ch = rem - row * 10;
        uint32_t dst = sb + (split ? SM_ALO : SM_AHI) + row * (A_PITCH * 2) + ch * 16;
        const __nv_bfloat16* src = (split ? g_xlo : g_xhi)
            + ((size_t)b * TPAD + tt * 128 + row) * MM + ch * 8;
        cp16(dst, src);
    }
    cp_commit();

    for (int i = tid; i < 192 * MM; i += GXT) {
        int g = i / MM, m = i - g * MM;
        float v = W_ih[(size_t)(gbase + g) * MM + m];
        __nv_bfloat16 h = __float2bfloat16(v);
        __nv_bfloat16 l = __float2bfloat16(v - __bfloat162float(h));
        *(__nv_bfloat16*)(sm + SM_WHI + (size_t)(g * W_PITCH + m) * 2) = h;
        *(__nv_bfloat16*)(sm + SM_WLO + (size_t)(g * W_PITCH + m) * 2) = l;
    }
    cp_wait0();
    __syncthreads();

    const int r0 = w * 16 + grp;
    uint32_t ahi[20], alo[20];
    #pragma unroll
    for (int ks = 0; ks < 5; ks++) {
        int c = 16 * ks + 2 * q;
        ahi[4 * ks + 0] = lds_pair(sm + SM_AHI, r0,     c,     A_PITCH);
        ahi[4 * ks + 1] = lds_pair(sm + SM_AHI, r0 + 8, c,     A_PITCH);
        ahi[4 * ks + 2] = lds_pair(sm + SM_AHI, r0,     c + 8, A_PITCH);
        ahi[4 * ks + 3] = lds_pair(sm + SM_AHI, r0 + 8, c + 8, A_PITCH);
        alo[4 * ks + 0] = lds_pair(sm + SM_ALO, r0,     c,     A_PITCH);
        alo[4 * ks + 1] = lds_pair(sm + SM_ALO, r0 + 8, c,     A_PITCH);
        alo[4 * ks + 2] = lds_pair(sm + SM_ALO, r0,     c + 8, A_PITCH);
        alo[4 * ks + 3] = lds_pair(sm + SM_ALO, r0 + 8, c + 8, A_PITCH);
    }

    const int trow = tt * 128 + w * 16 + grp;
    float* dst = g_gx + ((size_t)b * TT + trow) * GG + gbase;
    float* dst8 = dst + 8 * GG;
    const bool v0 = (trow < TT);
    const bool v8 = (trow + 8 < TT);

    for (int gp = 0; gp < 12; gp++) {
        float acc0[4] = {0.f, 0.f, 0.f, 0.f};
        float acc1[4] = {0.f, 0.f, 0.f, 0.f};
        const int gA = gp * 16 + grp;
        const int gB = gp * 16 + 8 + grp;
        #pragma unroll
        for (int ks = 0; ks < 5; ks++) {
            int c = 16 * ks + 2 * q;
            uint32_t bh0a = lds_pair(sm + SM_WHI, gA, c,     W_PITCH);
            uint32_t bh0b = lds_pair(sm + SM_WHI, gA, c + 8, W_PITCH);
            uint32_t bh1a = lds_pair(sm + SM_WHI, gB, c,     W_PITCH);
            uint32_t bh1b = lds_pair(sm + SM_WHI, gB, c + 8, W_PITCH);
            mma16816(acc0, ahi[4*ks], ahi[4*ks+1], ahi[4*ks+2], ahi[4*ks+3], bh0a, bh0b);
            mma16816(acc1, ahi[4*ks], ahi[4*ks+1], ahi[4*ks+2], ahi[4*ks+3], bh1a, bh1b);
            mma16816(acc0, alo[4*ks], alo[4*ks+1], alo[4*ks+2], alo[4*ks+3], bh0a, bh0b);
            mma16816(acc1, alo[4*ks], alo[4*ks+1], alo[4*ks+2], alo[4*ks+3], bh1a, bh1b);
            uint32_t bl0a = lds_pair(sm + SM_WLO, gA, c,     W_PITCH);
            uint32_t bl0b = lds_pair(sm + SM_WLO, gA, c + 8, W_PITCH);
            uint32_t bl1a = lds_pair(sm + SM_WLO, gB, c,     W_PITCH);
            uint32_t bl1b = lds_pair(sm + SM_WLO, gB, c + 8, W_PITCH);
            mma16816(acc0, ahi[4*ks], ahi[4*ks+1], ahi[4*ks+2], ahi[4*ks+3], bl0a, bl0b);
            mma16816(acc1, ahi[4*ks], ahi[4*ks+1], ahi[4*ks+2], ahi[4*ks+3], bl1a, bl1b);
        }
        const int col0 = gp * 16 + 2 * q;
        if (v0) {
            *(float2*)(dst + col0)     = make_float2(acc0[0], acc0[1]);
            *(float2*)(dst + col0 + 8) = make_float2(acc1[0], acc1[1]);
        }
        if (v8) {
            *(float2*)(dst8 + col0)     = make_float2(acc0[2], acc0[3]);
            *(float2*)(dst8 + col0 + 8) = make_float2(acc1[2], acc1[3]);
        }
    }
}

// ================= gru: warp-specialized fp16 HMMA (named barriers) ===========
// 64 blocks x 512 threads: warps 0..11 = mma (2 m-tiles each, W fp16 in regs);
// warps 12..15 = gates (128 thr, each owns (gb, jp) and (gb+2, jp)).
// Handshake: mma STS ghs -> bar.arrive(1) -> bar.sync(2);
//            gates bar.sync(1) -> gates/STS hb -> bar.arrive(2).
// Single-buffered ghs/hb is safe: reads complete before the matching arrive.
#define GRUT 512
#define BARCNT 512

__global__ __launch_bounds__(GRUT, 1)
void gru_hmma_kernel(const float* __restrict__ W_hh,
                     const float* __restrict__ b_ih,
                     const float* __restrict__ b_hh,
                     float* __restrict__ out)
{
    __shared__ uint32_t hbw[8 * 136];        // u64[8][68] view (B fragments)
    __shared__ float ghs[8 * 388];

    const int tid = threadIdx.x;
    const int lane = tid & 31;
    const int wid = tid >> 5;
    const int grp = lane >> 2;
    const int q = lane & 3;
    const int b0 = blockIdx.x * 4;
    const bool is_mma = (wid < 12);

    // ---- mma-warp W fragments (fp16), both m-tiles in registers ----
    uint32_t whi0[8][4], whi1[8][4];
    const int m0 = (wid < 12 ? wid : 0) * 32;
    if (is_mma) {
        #pragma unroll
        for (int kt = 0; kt < 8; kt++) {
            #pragma unroll
            for (int r = 0; r < 4; r++) {
                int row = m0 + grp + (r & 1) * 8;
                int col = kt * 16 + 2 * q + (r >> 1) * 8;
                float f0 = __ldg(W_hh + (size_t)row * HH + col);
                float f1 = __ldg(W_hh + (size_t)row * HH + col + 1);
                whi0[kt][r] = f16_pack(f0, f1);
                float g0 = __ldg(W_hh + (size_t)(row + 16) * HH + col);
                float g1 = __ldg(W_hh + (size_t)(row + 16) * HH + col + 1);
                whi1[kt][r] = f16_pack(g0, g1);
            }
        }
    }
    // h0 = 0
    for (int idx = tid; idx < 8 * 136; idx += GRUT) {
        hbw[idx] = 0u;
    }

    // ---- gate-warp setup (threads 384..511 -> gt 0..127) ----
    const int gt = tid - 384;
    const int gb = (gt >> 6) & 1;            // unit0 batch gb, unit1 batch gb+2
    const int jp = gt & 63;
    const int j = 2 * jp;
    const int ktj = jp >> 3, uj = jp & 7;
    const int slot = (uj < 4) ? (2 * (ktj * 8 + uj)) : (2 * (ktj * 8 + (uj - 4)) + 1);
    const int hiw0 = gb * 136 + slot,       low0 = (gb + 4) * 136 + slot;
    const int hiw1 = (gb + 2) * 136 + slot, low1 = (gb + 6) * 136 + slot;

    float br0 = 0.f, br1 = 0.f, bz0 = 0.f, bz1 = 0.f, bn0 = 0.f, bn1 = 0.f;
    float bhn0 = 0.f, bhn1 = 0.f;
    float hA0 = 0.f, hA1 = 0.f, hB0 = 0.f, hB1 = 0.f;
    const float* gxpA = g_gx + ((size_t)(b0 + (gb & 1)) * TT) * GG + j;
    const float* gxpB = g_gx + ((size_t)(b0 + 2 + (gb & 1)) * TT) * GG + j;
    float2 crA = make_float2(0.f, 0.f), czA = crA, cnA = crA;
    float2 crB = crA, czB = crA, cnB = crA;
    if (!is_mma) {
        br0 = __ldg(b_ih + j)          + __ldg(b_hh + j);
        br1 = __ldg(b_ih + j + 1)      + __ldg(b_hh + j + 1);
        bz0 = __ldg(b_ih + HH + j)     + __ldg(b_hh + HH + j);
        bz1 = __ldg(b_ih + HH + j + 1) + __ldg(b_hh + HH + j + 1);
        bn0 = __ldg(b_ih + 2 * HH + j);     bhn0 = __ldg(b_hh + 2 * HH + j);
        bn1 = __ldg(b_ih + 2 * HH + j + 1); bhn1 = __ldg(b_hh + 2 * HH + j + 1);
        crA = __ldg((const float2*)(gxpA));
        czA = __ldg((const float2*)(gxpA + HH));
        cnA = __ldg((const float2*)(gxpA + 2 * HH));
        crB = __ldg((const float2*)(gxpB));
        czB = __ldg((const float2*)(gxpB + HH));
        cnB = __ldg((const float2*)(gxpB + 2 * HH));
    }
    __syncthreads();

    const unsigned long long* hb64 = (const unsigned long long*)hbw;

    if (is_mma) {
        for (int t = 0; t < TT; t++) {
            float C0a[4] = {0.f, 0.f, 0.f, 0.f};
            float C0b[4] = {0.f, 0.f, 0.f, 0.f};
            float C1a[4] = {0.f, 0.f, 0.f, 0.f};
            float C1b[4] = {0.f, 0.f, 0.f, 0.f};
            #pragma unroll
            for (int kt = 0; kt < 8; kt += 2) {
                unsigned long long ba  = hb64[grp * 68 + kt * 8 + q];
                unsigned long long bbv = hb64[grp * 68 + (kt + 1) * 8 + q];
                uint32_t a0 = (uint32_t)ba,  a1 = (uint32_t)(ba >> 32);
                uint32_t c0 = (uint32_t)bbv, c1 = (uint32_t)(bbv >> 32);
                mma16816h(C0a, whi0[kt][0],   whi0[kt][1],   whi0[kt][2],   whi0[kt][3],   a0, a1);
                mma16816h(C0b, whi0[kt+1][0], whi0[kt+1][1], whi0[kt+1][2], whi0[kt+1][3], c0, c1);
                mma16816h(C1a, whi1[kt][0],   whi1[kt][1],   whi1[kt][2],   whi1[kt][3],   a0, a1);
                mma16816h(C1b, whi1[kt+1][0], whi1[kt+1][1], whi1[kt+1][2], whi1[kt+1][3], c0, c1);
            }
            ghs[(2 * q)     * 388 + m0 + grp]          = C0a[0] + C0b[0];
            ghs[(2 * q + 1) * 388 + m0 + grp]          = C0a[1] + C0b[1];
            ghs[(2 * q)     * 388 + m0 + grp + 8]      = C0a[2] + C0b[2];
            ghs[(2 * q + 1) * 388 + m0 + grp + 8]      = C0a[3] + C0b[3];
            ghs[(2 * q)     * 388 + m0 + 16 + grp]     = C1a[0] + C1b[0];
            ghs[(2 * q + 1) * 388 + m0 + 16 + grp]     = C1a[1] + C1b[1];
            ghs[(2 * q)     * 388 + m0 + 16 + grp + 8] = C1a[2] + C1b[2];
            ghs[(2 * q + 1) * 388 + m0 + 16 + grp + 8] = C1a[3] + C1b[3];
            BAR_ARRIVE(1, BARCNT);           // gh(t) ready
            BAR_SYNC(2, BARCNT);             // wait h(t+1)
        }
    } else {
        for (int t = 0; t < TT; t++) {
            // prefetch next gx while mma phase runs (before blocking)
            const size_t tn = (t + 1 < TT) ? (size_t)(t + 1) : (size_t)t;
            const float* pA = gxpA + tn * GG;
            const float* pB = gxpB + tn * GG;
            float2 nrA = __ldg((const float2*)(pA));
            float2 nzA = __ldg((const float2*)(pA + HH));
            float2 nnA = __ldg((const float2*)(pA + 2 * HH));
            float2 nrB = __ldg((const float2*)(pB));
            float2 nzB = __ldg((const float2*)(pB + HH));
            float2 nnB = __ldg((const float2*)(pB + 2 * HH));
            // precompute gx + bias sums (off critical path)
            float prA0 = crA.x + br0, prA1 = crA.y + br1;
            float pzA0 = czA.x + bz0, pzA1 = czA.y + bz1;
            float pnA0 = cnA.x + bn0, pnA1 = cnA.y + bn1;
            float prB0 = crB.x + br0, prB1 = crB.y + br1;
            float pzB0 = czB.x + bz0, pzB1 = czB.y + bz1;
            float pnB0 = cnB.x + bn0, pnB1 = cnB.y + bn1;

            BAR_SYNC(1, BARCNT);             // wait gh(t)
            // unit A: batch gb
            {
                const float* gA = &ghs[gb * 388];
                const float* gB = &ghs[(gb + 4) * 388];
                float2 ra = *(const float2*)(gA + j);
                float2 rb = *(const float2*)(gB + j);
                float2 za = *(const float2*)(gA + HH + j);
                float2 zb = *(const float2*)(gB + HH + j);
                float2 na = *(const float2*)(gA + 2 * HH + j);
                float2 nb = *(const float2*)(gB + 2 * HH + j);
                float r0 = fast_sigmoid(prA0 + ra.x + rb.x);
                float r1 = fast_sigmoid(prA1 + ra.y + rb.y);
                float z0 = fast_sigmoid(pzA0 + za.x + zb.x);
                float z1 = fast_sigmoid(pzA1 + za.y + zb.y);
                float n0 = fast_tanh(pnA0 + r0 * (na.x + nb.x + bhn0));
                float n1 = fast_tanh(pnA1 + r1 * (na.y + nb.y + bhn1));
                hA0 = fmaf(z0, hA0 - n0, n0);
                hA1 = fmaf(z1, hA1 - n1, n1);
                hbw[hiw0] = f16_pack(hA0, hA1);
                hbw[low0] = f16_lo_pack(hA0, hA1);
            }
            // unit B: batch gb+2
            {
                const float* gA = &ghs[(gb + 2) * 388];
                const float* gB = &ghs[(gb + 6) * 388];
                float2 ra = *(const float2*)(gA + j);
                float2 rb = *(const float2*)(gB + j);
                float2 za = *(const float2*)(gA + HH + j);
                float2 zb = *(const float2*)(gB + HH + j);
                float2 na = *(const float2*)(gA + 2 * HH + j);
                float2 nb = *(const float2*)(gB + 2 * HH + j);
                float r0 = fast_sigmoid(prB0 + ra.x + rb.x);
                float r1 = fast_sigmoid(prB1 + ra.y + rb.y);
                float z0 = fast_sigmoid(pzB0 + za.x + zb.x);
                float z1 = fast_sigmoid(pzB1 + za.y + zb.y);
                float n0 = fast_tanh(pnB0 + r0 * (na.x + nb.x + bhn0));
                float n1 = fast_tanh(pnB1 + r1 * (na.y + nb.y + bhn1));
                hB0 = fmaf(z0, hB0 - n0, n0);
                hB1 = fmaf(z1, hB1 - n1, n1);
                hbw[hiw1] = f16_pack(hB0, hB1);
                hbw[low1] = f16_lo_pack(hB0, hB1);
            }
            BAR_ARRIVE(2, BARCNT);           // h(t+1) ready
            crA = nrA; czA = nzA; cnA = nnA;
            crB = nrB; czB = nzB; cnB = nnB;
        }
    }

    if (!is_mma) {
        *(float2*)(out + (size_t)(b0 + gb) * HH + j)     = make_float2(hA0, hA1);
        *(float2*)(out + (size_t)(b0 + 2 + gb) * HH + j) = make_float2(hB0, hB1);
    }
}

// ================= launch =================
extern "C" void kernel_launch(void* const* d_in, const int* in_sizes, int n_in,
                              void* d_out, int out_size)
{
    const float* x    = (const float*)d_in[0];
    const float* W_ih = (const float*)d_in[1];
    const float* W_hh = (const float*)d_in[2];
    const float* b_ih = (const float*)d_in[3];
    const float* b_hh = (const float*)d_in[4];
    float* out = (float*)d_out;

    cudaFuncSetAttribute(gx_hmma_kernel,
                         cudaFuncAttributeMaxDynamicSharedMemorySize, GX_SMEM);

    prep_kernel<<<dim3(8, BB), PREP_THREADS>>>(x);
    gx_hmma_kernel<<<dim3(16, BB), GXT, GX_SMEM>>>(W_ih);
    gru_hmma_kernel<<<BB / 4, GRUT>>>(W_hh, b_ih, b_hh, out);
}

// round 13
// speedup vs baseline: 1.1113x; 1.1113x over previous
#include <cuda_runtime.h>
#include <cuda_bf16.h>
#include <cuda_fp16.h>
#include <cstdint>

#define BB 256
#define MM 80
#define TT 1000
#define HH 128
#define GG 384
#define TPAD 1024

// ---------------- device scratch ----------------
__device__ float g_gx[(size_t)BB * TT * GG];                // 393 MB
__device__ __nv_bfloat16 g_xhi[(size_t)BB * TPAD * MM];     // 42 MB
__device__ __nv_bfloat16 g_xlo[(size_t)BB * TPAD * MM];     // 42 MB

// ---------------- helpers ----------------
__device__ __forceinline__ float fast_sigmoid(float x) {
    float e = __expf(-x);
    return __fdividef(1.0f, 1.0f + e);
}
__device__ __forceinline__ float fast_tanh(float x) {
    float ax = fabsf(x);
    float e = __expf(-2.0f * ax);
    float t = __fdividef(1.0f - e, 1.0f + e);
    return copysignf(t, x);
}
__device__ __forceinline__ void cp16(uint32_t saddr, const void* g) {
    asm volatile("cp.async.cg.shared.global [%0], [%1], 16;" :: "r"(saddr), "l"(g));
}
__device__ __forceinline__ void cp_commit() { asm volatile("cp.async.commit_group;" ::: "memory"); }
__device__ __forceinline__ void cp_wait0()  { asm volatile("cp.async.wait_group 0;" ::: "memory"); }
__device__ __forceinline__ uint32_t smem_u32(const void* p) {
    uint32_t a;
    asm("{ .reg .u64 t; cvta.to.shared.u64 t, %1; cvt.u32.u64 %0, t; }" : "=r"(a) : "l"(p));
    return a;
}
// bf16 mma (gx kernel)
__device__ __forceinline__ void mma16816(float* c, uint32_t a0, uint32_t a1,
                                         uint32_t a2, uint32_t a3,
                                         uint32_t b0, uint32_t b1) {
    asm("mma.sync.aligned.m16n8k16.row.col.f32.bf16.bf16.f32 "
        "{%0,%1,%2,%3}, {%4,%5,%6,%7}, {%8,%9}, {%0,%1,%2,%3};"
        : "+f"(c[0]), "+f"(c[1]), "+f"(c[2]), "+f"(c[3])
        : "r"(a0), "r"(a1), "r"(a2), "r"(a3), "r"(b0), "r"(b1));
}
// fp16 mma (gru kernel)
__device__ __forceinline__ void mma16816h(float* c, uint32_t a0, uint32_t a1,
                                          uint32_t a2, uint32_t a3,
                                          uint32_t b0, uint32_t b1) {
    asm("mma.sync.aligned.m16n8k16.row.col.f32.f16.f16.f32 "
        "{%0,%1,%2,%3}, {%4,%5,%6,%7}, {%8,%9}, {%0,%1,%2,%3};"
        : "+f"(c[0]), "+f"(c[1]), "+f"(c[2]), "+f"(c[3])
        : "r"(a0), "r"(a1), "r"(a2), "r"(a3), "r"(b0), "r"(b1));
}
__device__ __forceinline__ uint32_t f16_pack(float a, float b) {
    __half2 p = __floats2half2_rn(a, b);
    return reinterpret_cast<uint32_t&>(p);
}

// ================= prep: transpose + bf16 split =================
#define PREP_THREADS 256
__global__ __launch_bounds__(PREP_THREADS)
void prep_kernel(const float* __restrict__ x)
{
    __shared__ float xs[MM][129];
    const int b = blockIdx.y, t0 = blockIdx.x * 128;
    const int tid = threadIdx.x;

    for (int idx = tid; idx < MM * 128; idx += PREP_THREADS) {
        int m = idx >> 7, j = idx & 127;
        int t = t0 + j;
        xs[m][j] = (t < TT) ? x[((size_t)b * MM + m) * TT + t] : 0.0f;
    }
    __syncthreads();

    for (int idx = tid; idx < 128 * 10; idx += PREP_THREADS) {
        int j = idx / 10, mv = idx % 10;
        int m0 = mv * 8;
        __align__(16) __nv_bfloat16 hi[8];
        __align__(16) __nv_bfloat16 lo[8];
        #pragma unroll
        for (int u = 0; u < 8; u++) {
            float v = xs[m0 + u][j];
            __nv_bfloat16 h = __float2bfloat16(v);
            hi[u] = h;
            lo[u] = __float2bfloat16(v - __bfloat162float(h));
        }
        size_t off = ((size_t)b * TPAD + t0 + j) * MM + m0;
        *(uint4*)(g_xhi + off) = *(const uint4*)hi;
        *(uint4*)(g_xlo + off) = *(const uint4*)lo;
    }
}

// ================= gx via mma.sync HMMA (split-bf16, 3 terms) =================
#define GXT 256
#define A_PITCH 88
#define W_PITCH 84
#define SM_AHI 0
#define SM_ALO (128 * A_PITCH * 2)
#define SM_WHI (SM_ALO + 128 * A_PITCH * 2)
#define SM_WLO (SM_WHI + 192 * W_PITCH * 2)
#define GX_SMEM (SM_WLO + 192 * W_PITCH * 2)

__device__ __forceinline__ uint32_t lds_pair(const char* base, int row, int col, int pitch) {
    return *(const uint32_t*)(base + (size_t)(row * pitch + col) * 2);
}

__global__ __launch_bounds__(GXT)
void gx_hmma_kernel(const float* __restrict__ W_ih)
{
    extern __shared__ char sm[];
    const int tid = threadIdx.x;
    const int lane = tid & 31;
    const int w = tid >> 5;
    const int grp = lane >> 2;
    const int q = lane & 3;
    const int tt = blockIdx.x >> 1;
    const int ghalf = blockIdx.x & 1;
    const int gbase = ghalf * 192;
    const int b = blockIdx.y;
    const uint32_t sb = smem_u32(sm);

    for (int i = tid; i < 2560; i += GXT) {
        int split = i / 1280;
        int rem = i - split * 1280;
        int row = rem / 10, ch = rem - row * 10;
        uint32_t dst = sb + (split ? SM_ALO : SM_AHI) + row * (A_PITCH * 2) + ch * 16;
        const __nv_bfloat16* src = (split ? g_xlo : g_xhi)
            + ((size_t)b * TPAD + tt * 128 + row) * MM + ch * 8;
        cp16(dst, src);
    }
    cp_commit();

    for (int i = tid; i < 192 * MM; i += GXT) {
        int g = i / MM, m = i - g * MM;
        float v = W_ih[(size_t)(gbase + g) * MM + m];
        __nv_bfloat16 h = __float2bfloat16(v);
        __nv_bfloat16 l = __float2bfloat16(v - __bfloat162float(h));
        *(__nv_bfloat16*)(sm + SM_WHI + (size_t)(g * W_PITCH + m) * 2) = h;
        *(__nv_bfloat16*)(sm + SM_WLO + (size_t)(g * W_PITCH + m) * 2) = l;
    }
    cp_wait0();
    __syncthreads();

    const int r0 = w * 16 + grp;
    uint32_t ahi[20], alo[20];
    #pragma unroll
    for (int ks = 0; ks < 5; ks++) {
        int c = 16 * ks + 2 * q;
        ahi[4 * ks + 0] = lds_pair(sm + SM_AHI, r0,     c,     A_PITCH);
        ahi[4 * ks + 1] = lds_pair(sm + SM_AHI, r0 + 8, c,     A_PITCH);
        ahi[4 * ks + 2] = lds_pair(sm + SM_AHI, r0,     c + 8, A_PITCH);
        ahi[4 * ks + 3] = lds_pair(sm + SM_AHI, r0 + 8, c + 8, A_PITCH);
        alo[4 * ks + 0] = lds_pair(sm + SM_ALO, r0,     c,     A_PITCH);
        alo[4 * ks + 1] = lds_pair(sm + SM_ALO, r0 + 8, c,     A_PITCH);
        alo[4 * ks + 2] = lds_pair(sm + SM_ALO, r0,     c + 8, A_PITCH);
        alo[4 * ks + 3] = lds_pair(sm + SM_ALO, r0 + 8, c + 8, A_PITCH);
    }

    const int trow = tt * 128 + w * 16 + grp;
    float* dst = g_gx + ((size_t)b * TT + trow) * GG + gbase;
    float* dst8 = dst + 8 * GG;
    const bool v0 = (trow < TT);
    const bool v8 = (trow + 8 < TT);

    for (int gp = 0; gp < 12; gp++) {
        float acc0[4] = {0.f, 0.f, 0.f, 0.f};
        float acc1[4] = {0.f, 0.f, 0.f, 0.f};
        const int gA = gp * 16 + grp;
        const int gB = gp * 16 + 8 + grp;
        #pragma unroll
        for (int ks = 0; ks < 5; ks++) {
            int c = 16 * ks + 2 * q;
            uint32_t bh0a = lds_pair(sm + SM_WHI, gA, c,     W_PITCH);
            uint32_t bh0b = lds_pair(sm + SM_WHI, gA, c + 8, W_PITCH);
            uint32_t bh1a = lds_pair(sm + SM_WHI, gB, c,     W_PITCH);
            uint32_t bh1b = lds_pair(sm + SM_WHI, gB, c + 8, W_PITCH);
            mma16816(acc0, ahi[4*ks], ahi[4*ks+1], ahi[4*ks+2], ahi[4*ks+3], bh0a, bh0b);
            mma16816(acc1, ahi[4*ks], ahi[4*ks+1], ahi[4*ks+2], ahi[4*ks+3], bh1a, bh1b);
            mma16816(acc0, alo[4*ks], alo[4*ks+1], alo[4*ks+2], alo[4*ks+3], bh0a, bh0b);
            mma16816(acc1, alo[4*ks], alo[4*ks+1], alo[4*ks+2], alo[4*ks+3], bh1a, bh1b);
            uint32_t bl0a = lds_pair(sm + SM_WLO, gA, c,     W_PITCH);
            uint32_t bl0b = lds_pair(sm + SM_WLO, gA, c + 8, W_PITCH);
            uint32_t bl1a = lds_pair(sm + SM_WLO, gB, c,     W_PITCH);
            uint32_t bl1b = lds_pair(sm + SM_WLO, gB, c + 8, W_PITCH);
            mma16816(acc0, ahi[4*ks], ahi[4*ks+1], ahi[4*ks+2], ahi[4*ks+3], bl0a, bl0b);
            mma16816(acc1, ahi[4*ks], ahi[4*ks+1], ahi[4*ks+2], ahi[4*ks+3], bl1a, bl1b);
        }
        const int col0 = gp * 16 + 2 * q;
        if (v0) {
            *(float2*)(dst + col0)     = make_float2(acc0[0], acc0[1]);
            *(float2*)(dst + col0 + 8) = make_float2(acc1[0], acc1[1]);
        }
        if (v8) {
            *(float2*)(dst8 + col0)     = make_float2(acc0[2], acc0[3]);
            *(float2*)(dst8 + col0 + 8) = make_float2(acc1[2], acc1[3]);
        }
    }
}

// ================= gru: gate-aligned fp16 HMMA, ONE barrier/step ==============
// 64 blocks x 256 threads (8 warps). Warp w owns m-tiles {w, w+8, w+16} =
// rows j in [16w,16w+16) of gates r, z, n. n=8 B cols = [h_hi b0..3 | h_lo b0..3].
// After MMA, thread (grp,q) holds r/z/n for ITS OWN j => gates fully in-warp:
// shfl_xor(2) combines hi+lo cols, gates computed per-lane (2 batch units),
// h stored as fp16 hi/lo via 4 STS.16. Double-buffered hb, one __syncthreads.
#define GRUT 256

__global__ __launch_bounds__(GRUT, 1)
void gru_hmma_kernel(const float* __restrict__ W_hh,
                     const float* __restrict__ b_ih,
                     const float* __restrict__ b_hh,
                     float* __restrict__ out)
{
    __shared__ __align__(16) uint32_t hbw[2][8 * 136];   // u64[8][68] views

    const int tid = threadIdx.x;
    const int lane = tid & 31;
    const int wid = tid >> 5;                // 0..7
    const int grp = lane >> 2;
    const int q = lane & 3;
    const int b0 = blockIdx.x * 4;

    // ---- W fragments (fp16) for the 3 gate tiles of this warp ----
    uint32_t wr[8][4], wz[8][4], wn[8][4];
    {
        const int mr = 16 * wid;
        const int mz = 128 + 16 * wid;
        const int mn = 256 + 16 * wid;
        #pragma unroll
        for (int kt = 0; kt < 8; kt++) {
            #pragma unroll
            for (int r = 0; r < 4; r++) {
                int ro = grp + (r & 1) * 8;
                int col = kt * 16 + 2 * q + (r >> 1) * 8;
                wr[kt][r] = f16_pack(__ldg(W_hh + (size_t)(mr + ro) * HH + col),
                                     __ldg(W_hh + (size_t)(mr + ro) * HH + col + 1));
                wz[kt][r] = f16_pack(__ldg(W_hh + (size_t)(mz + ro) * HH + col),
                                     __ldg(W_hh + (size_t)(mz + ro) * HH + col + 1));
                wn[kt][r] = f16_pack(__ldg(W_hh + (size_t)(mn + ro) * HH + col),
                                     __ldg(W_hh + (size_t)(mn + ro) * HH + col + 1));
            }
        }
    }

    // ---- per-lane gate identity ----
    const int j  = 16 * wid + grp + ((q >= 2) ? 8 : 0);   // hidden index
    const int bb = 2 * (q & 1);                           // batch pair {bb, bb+1}
    const float br  = __ldg(b_ih + j)        + __ldg(b_hh + j);
    const float bz  = __ldg(b_ih + HH + j)   + __ldg(b_hh + HH + j);
    const float bni = __ldg(b_ih + 2 * HH + j);
    const float bhn = __ldg(b_hh + 2 * HH + j);

    // h-store slots (u16 view): validated slot formula specialization
    const int slot = 2 * (8 * wid + (grp >> 1)) + ((q >= 2) ? 1 : 0);
    const int par  = grp & 1;

    // gx streams for the two batches
    const float* gx0 = g_gx + ((size_t)(b0 + bb) * TT) * GG + j;
    const float* gx1 = g_gx + ((size_t)(b0 + bb + 1) * TT) * GG + j;
    float c0r = __ldg(gx0), c0z = __ldg(gx0 + HH), c0n = __ldg(gx0 + 2 * HH);
    float c1r = __ldg(gx1), c1z = __ldg(gx1 + HH), c1n = __ldg(gx1 + 2 * HH);
    float h0 = 0.0f, h1 = 0.0f;

    // zero buffer 0 (h(0) = 0); buffer 1 fully written each step
    for (int idx = tid; idx < 8 * 136; idx += GRUT) hbw[0][idx] = 0u;
    __syncthreads();

    for (int t = 0; t < TT; t++) {
        // prefetch gx(t+1) — consumed next step; covered by ~1 full step
        const size_t tn = (t + 1 < TT) ? (size_t)(t + 1) : (size_t)t;
        float n0r = __ldg(gx0 + tn * GG);
        float n0z = __ldg(gx0 + tn * GG + HH);
        float n0n = __ldg(gx0 + tn * GG + 2 * HH);
        float n1r = __ldg(gx1 + tn * GG);
        float n1z = __ldg(gx1 + tn * GG + HH);
        float n1n = __ldg(gx1 + tn * GG + 2 * HH);

        // ---- mma: 3 gate tiles x 8 kt, shared B operands ----
        const unsigned long long* hb = (const unsigned long long*)hbw[t & 1];
        float Cr[4] = {0.f, 0.f, 0.f, 0.f};
        float Cz[4] = {0.f, 0.f, 0.f, 0.f};
        float Cn[4] = {0.f, 0.f, 0.f, 0.f};
        #pragma unroll
        for (int kt = 0; kt < 8; kt++) {
            unsigned long long bv = hb[grp * 68 + kt * 8 + q];
            uint32_t bv0 = (uint32_t)bv;
            uint32_t bv1 = (uint32_t)(bv >> 32);
            mma16816h(Cr, wr[kt][0], wr[kt][1], wr[kt][2], wr[kt][3], bv0, bv1);
            mma16816h(Cz, wz[kt][0], wz[kt][1], wz[kt][2], wz[kt][3], bv0, bv1);
            mma16816h(Cn, wn[kt][0], wn[kt][1], wn[kt][2], wn[kt][3], bv0, bv1);
        }
        // combine hi (cols 0..3) + lo (cols 4..7): q <-> q^2
        #pragma unroll
        for (int i = 0; i < 4; i++) {
            Cr[i] += __shfl_xor_sync(0xffffffffu, Cr[i], 2, 32);
            Cz[i] += __shfl_xor_sync(0xffffffffu, Cz[i], 2, 32);
            Cn[i] += __shfl_xor_sync(0xffffffffu, Cn[i], 2, 32);
        }
        const bool hi_half = (q < 2);       // rows grp (C[0..1]) vs grp+8 (C[2..3])
        float ghr0 = hi_half ? Cr[0] : Cr[2];
        float ghr1 = hi_half ? Cr[1] : Cr[3];
        float ghz0 = hi_half ? Cz[0] : Cz[2];
        float ghz1 = hi_half ? Cz[1] : Cz[3];
        float ghn0 = hi_half ? Cn[0] : Cn[2];
        float ghn1 = hi_half ? Cn[1] : Cn[3];

        // ---- gates (2 units: batches bb, bb+1, same j) ----
        {
            float r0 = fast_sigmoid(c0r + br + ghr0);
            float z0 = fast_sigmoid(c0z + bz + ghz0);
            float nn0 = fast_tanh(c0n + bni + r0 * (ghn0 + bhn));
            h0 = fmaf(z0, h0 - nn0, nn0);
            float r1 = fast_sigmoid(c1r + br + ghr1);
            float z1 = fast_sigmoid(c1z + bz + ghz1);
            float nn1 = fast_tanh(c1n + bni + r1 * (ghn1 + bhn));
            h1 = fmaf(z1, h1 - nn1, nn1);
        }

        // ---- store h as fp16 hi/lo into the other buffer ----
        {
            uint16_t* dst = (uint16_t*)hbw[(t & 1) ^ 1];
            __half hh0 = __float2half_rn(h0);
            __half hh1 = __float2half_rn(h1);
            float l0 = h0 - __half2float(hh0);
            float l1 = h1 - __half2float(hh1);
            __half hl0 = __float2half_rn(l0);
            __half hl1 = __float2half_rn(l1);
            dst[2 * ((bb)     * 136 + slot) + par] = __half_as_ushort(hh0);
            dst[2 * ((bb + 4) * 136 + slot) + par] = __half_as_ushort(hl0);
            dst[2 * ((bb + 1) * 136 + slot) + par] = __half_as_ushort(hh1);
            dst[2 * ((bb + 5) * 136 + slot) + par] = __half_as_ushort(hl1);
        }
        c0r = n0r; c0z = n0z; c0n = n0n;
        c1r = n1r; c1z = n1z; c1n = n1n;
        __syncthreads();
    }

    out[(size_t)(b0 + bb) * HH + j]     = h0;
    out[(size_t)(b0 + bb + 1) * HH + j] = h1;
}

// ================= launch =================
extern "C" void kernel_launch(void* const* d_in, const int* in_sizes, int n_in,
                              void* d_out, int out_size)
{
    const float* x    = (const float*)d_in[0];
    const float* W_ih = (const float*)d_in[1];
    const float* W_hh = (const float*)d_in[2];
    const float* b_ih = (const float*)d_in[3];
    const float* b_hh = (const float*)d_in[4];
    float* out = (float*)d_out;

    cudaFuncSetAttribute(gx_hmma_kernel,
                         cudaFuncAttributeMaxDynamicSharedMemorySize, GX_SMEM);

    prep_kernel<<<dim3(8, BB), PREP_THREADS>>>(x);
    gx_hmma_kernel<<<dim3(16, BB), GXT, GX_SMEM>>>(W_ih);
    gru_hmma_kernel<<<BB / 4, GRUT>>>(W_hh, b_ih, b_hh, out);
}

// round 14
// speedup vs baseline: 1.3056x; 1.1749x over previous
#include <cuda_runtime.h>
#include <cuda_bf16.h>
#include <cuda_fp16.h>
#include <cstdint>

#define BB 256
#define MM 80
#define TT 1000
#define HH 128
#define GG 384

// ---------------- device scratch ----------------
__device__ float g_gx[(size_t)BB * TT * GG];                // 393 MB

// ---------------- helpers ----------------
__device__ __forceinline__ float fast_tanh(float x) {
    float ax = fabsf(x);
    float e = __expf(-2.0f * ax);
    float t = __fdividef(1.0f - e, 1.0f + e);
    return copysignf(t, x);
}
// sigmoid via single-instruction tanh.approx: sig(x) = 0.5*tanh(0.5x) + 0.5
__device__ __forceinline__ float sig_t(float x) {
    float t;
    asm("tanh.approx.f32 %0, %1;" : "=f"(t) : "f"(0.5f * x));
    return fmaf(0.5f, t, 0.5f);
}
__device__ __forceinline__ uint32_t smem_u32(const void* p) {
    uint32_t a;
    asm("{ .reg .u64 t; cvta.to.shared.u64 t, %1; cvt.u32.u64 %0, t; }" : "=r"(a) : "l"(p));
    return a;
}
// bf16 mma (gx kernel)
__device__ __forceinline__ void mma16816(float* c, uint32_t a0, uint32_t a1,
                                         uint32_t a2, uint32_t a3,
                                         uint32_t b0, uint32_t b1) {
    asm("mma.sync.aligned.m16n8k16.row.col.f32.bf16.bf16.f32 "
        "{%0,%1,%2,%3}, {%4,%5,%6,%7}, {%8,%9}, {%0,%1,%2,%3};"
        : "+f"(c[0]), "+f"(c[1]), "+f"(c[2]), "+f"(c[3])
        : "r"(a0), "r"(a1), "r"(a2), "r"(a3), "r"(b0), "r"(b1));
}
// fp16 mma (gru kernel)
__device__ __forceinline__ void mma16816h(float* c, uint32_t a0, uint32_t a1,
                                          uint32_t a2, uint32_t a3,
                                          uint32_t b0, uint32_t b1) {
    asm("mma.sync.aligned.m16n8k16.row.col.f32.f16.f16.f32 "
        "{%0,%1,%2,%3}, {%4,%5,%6,%7}, {%8,%9}, {%0,%1,%2,%3};"
        : "+f"(c[0]), "+f"(c[1]), "+f"(c[2]), "+f"(c[3])
        : "r"(a0), "r"(a1), "r"(a2), "r"(a3), "r"(b0), "r"(b1));
}
__device__ __forceinline__ uint32_t bf16_pack2(float a, float b) {
    uint32_t ua = (uint32_t)__bfloat16_as_ushort(__float2bfloat16(a));
    uint32_t ub = (uint32_t)__bfloat16_as_ushort(__float2bfloat16(b));
    return ua | (ub << 16);
}
__device__ __forceinline__ uint32_t f16_pack(float a, float b) {
    __half2 p = __floats2half2_rn(a, b);
    return reinterpret_cast<uint32_t&>(p);
}
__device__ __forceinline__ uint32_t f16_lo_pack(float a, float b) {
    float ra = a - __half2float(__float2half_rn(a));
    float rb = b - __half2float(__float2half_rn(b));
    return f16_pack(ra, rb);
}

// ================= gx via mma.sync HMMA, fused transpose+split ================
// grid (16, 256): blockIdx.x = tt*2 + ghalf ; 256 threads (8 warps).
// Loads x tile [80 m][128 t] directly (coalesced), transposes via fp32 smem,
// builds split-bf16 A fragments in registers with in-kernel cvt.
#define GXT 256
#define XS_PITCH 132
#define W_PITCH 84
#define SM_XS 0
#define SM_WHI (MM * XS_PITCH * 4)                    // 42240
#define SM_WLO (SM_WHI + 192 * W_PITCH * 2)           // +32256
#define GX_SMEM (SM_WLO + 192 * W_PITCH * 2)          // 106752

__device__ __forceinline__ uint32_t lds_pair(const char* base, int row, int col, int pitch) {
    return *(const uint32_t*)(base + (size_t)(row * pitch + col) * 2);
}

__global__ __launch_bounds__(GXT)
void gx_hmma_kernel(const float* __restrict__ x,
                    const float* __restrict__ W_ih)
{
    extern __shared__ char sm[];
    float* xs = (float*)(sm + SM_XS);       // [MM][XS_PITCH], xs[m][t]
    const int tid = threadIdx.x;
    const int lane = tid & 31;
    const int w = tid >> 5;
    const int grp = lane >> 2;
    const int q = lane & 3;
    const int tt = blockIdx.x >> 1;
    const int ghalf = blockIdx.x & 1;
    const int gbase = ghalf * 192;
    const int b = blockIdx.y;
    const int t0 = tt * 128;

    // ---- load x tile [80][128] (t-contiguous, coalesced float4) ----
    for (int i = tid; i < MM * 32; i += GXT) {
        int m = i >> 5, seg = i & 31;
        int t = t0 + seg * 4;
        const float* src = x + ((size_t)b * MM + m) * TT + t;
        float4 v;
        if (t + 3 < TT) {
            v = *(const float4*)src;
        } else {
            v.x = (t     < TT) ? src[0] : 0.0f;
            v.y = (t + 1 < TT) ? src[1] : 0.0f;
            v.z = (t + 2 < TT) ? src[2] : 0.0f;
            v.w = (t + 3 < TT) ? src[3] : 0.0f;
        }
        float* d = xs + m * XS_PITCH + seg * 4;
        d[0] = v.x; d[1] = v.y; d[2] = v.z; d[3] = v.w;
    }

    // ---- W convert: fp32 -> split bf16, [192][W_PITCH] ----
    for (int i = tid; i < 192 * MM; i += GXT) {
        int g = i / MM, m = i - g * MM;
        float v = W_ih[(size_t)(gbase + g) * MM + m];
        __nv_bfloat16 h = __float2bfloat16(v);
        __nv_bfloat16 l = __float2bfloat16(v - __bfloat162float(h));
        *(__nv_bfloat16*)(sm + SM_WHI + (size_t)(g * W_PITCH + m) * 2) = h;
        *(__nv_bfloat16*)(sm + SM_WLO + (size_t)(g * W_PITCH + m) * 2) = l;
    }
    __syncthreads();

    // ---- build A fragments (split bf16) from fp32 smem ----
    const int r0 = w * 16 + grp;
    uint32_t ahi[20], alo[20];
    #pragma unroll
    for (int ks = 0; ks < 5; ks++) {
        int c = 16 * ks + 2 * q;
        #pragma unroll
        for (int r = 0; r < 4; r++) {
            int t = r0 + (r & 1) * 8;           // fragment row (time)
            int m = c + (r >> 1) * 8;           // fragment col pair (mel)
            float f0 = xs[m * XS_PITCH + t];
            float f1 = xs[(m + 1) * XS_PITCH + t];
            __nv_bfloat16 h0 = __float2bfloat16(f0);
            __nv_bfloat16 h1 = __float2bfloat16(f1);
            ahi[4 * ks + r] = (uint32_t)__bfloat16_as_ushort(h0)
                            | ((uint32_t)__bfloat16_as_ushort(h1) << 16);
            alo[4 * ks + r] = bf16_pack2(f0 - __bfloat162float(h0),
                                         f1 - __bfloat162float(h1));
        }
    }

    const int trow = t0 + w * 16 + grp;
    float* dst = g_gx + ((size_t)b * TT + trow) * GG + gbase;
    float* dst8 = dst + 8 * GG;
    const bool v0 = (trow < TT);
    const bool v8 = (trow + 8 < TT);

    for (int gp = 0; gp < 12; gp++) {
        float acc0[4] = {0.f, 0.f, 0.f, 0.f};
        float acc1[4] = {0.f, 0.f, 0.f, 0.f};
        const int gA = gp * 16 + grp;
        const int gB = gp * 16 + 8 + grp;
        #pragma unroll
        for (int ks = 0; ks < 5; ks++) {
            int c = 16 * ks + 2 * q;
            uint32_t bh0a = lds_pair(sm + SM_WHI, gA, c,     W_PITCH);
            uint32_t bh0b = lds_pair(sm + SM_WHI, gA, c + 8, W_PITCH);
            uint32_t bh1a = lds_pair(sm + SM_WHI, gB, c,     W_PITCH);
            uint32_t bh1b = lds_pair(sm + SM_WHI, gB, c + 8, W_PITCH);
            mma16816(acc0, ahi[4*ks], ahi[4*ks+1], ahi[4*ks+2], ahi[4*ks+3], bh0a, bh0b);
            mma16816(acc1, ahi[4*ks], ahi[4*ks+1], ahi[4*ks+2], ahi[4*ks+3], bh1a, bh1b);
            mma16816(acc0, alo[4*ks], alo[4*ks+1], alo[4*ks+2], alo[4*ks+3], bh0a, bh0b);
            mma16816(acc1, alo[4*ks], alo[4*ks+1], alo[4*ks+2], alo[4*ks+3], bh1a, bh1b);
            uint32_t bl0a = lds_pair(sm + SM_WLO, gA, c,     W_PITCH);
            uint32_t bl0b = lds_pair(sm + SM_WLO, gA, c + 8, W_PITCH);
            uint32_t bl1a = lds_pair(sm + SM_WLO, gB, c,     W_PITCH);
            uint32_t bl1b = lds_pair(sm + SM_WLO, gB, c + 8, W_PITCH);
            mma16816(acc0, ahi[4*ks], ahi[4*ks+1], ahi[4*ks+2], ahi[4*ks+3], bl0a, bl0b);
            mma16816(acc1, ahi[4*ks], ahi[4*ks+1], ahi[4*ks+2], ahi[4*ks+3], bl1a, bl1b);
        }
        const int col0 = gp * 16 + 2 * q;
        if (v0) {
            *(float2*)(dst + col0)     = make_float2(acc0[0], acc0[1]);
            *(float2*)(dst + col0 + 8) = make_float2(acc1[0], acc1[1]);
        }
        if (v8) {
            *(float2*)(dst8 + col0)     = make_float2(acc0[2], acc0[3]);
            *(float2*)(dst8 + col0 + 8) = make_float2(acc1[2], acc1[3]);
        }
    }
}

// ================= gru: 4-batch fp16 HMMA (R9 shape, approx sigmoids) =========
// 64 blocks x 384 threads (12 warps). Warp w owns m-tiles 2w, 2w+1.
// W fp16 fragments register-resident. n=8 B cols = [h_hi b0..3 | h_lo b0..3].
// gh = col[b] + col[b+4]. Gates: threads 0..255 (batch = tid>>6, j-pair = tid&63).
#define GRUT 384

__global__ __launch_bounds__(GRUT, 1)
void gru_hmma_kernel(const float* __restrict__ W_hh,
                     const float* __restrict__ b_ih,
                     const float* __restrict__ b_hh,
                     float* __restrict__ out)
{
    __shared__ uint32_t hbw[8 * 136];        // u64[8][68] view (B fragments)
    __shared__ float ghs[8 * 388];

    const int tid = threadIdx.x;
    const int lane = tid & 31;
    const int wid = tid >> 5;
    const int grp = lane >> 2;
    const int q = lane & 3;
    const int b0 = blockIdx.x * 4;
    const int m0 = wid * 32;                 // rows for this warp's two m-tiles

    // ---- W fragments (fp16), both m-tiles in registers ----
    uint32_t whi0[8][4], whi1[8][4];
    #pragma unroll
    for (int kt = 0; kt < 8; kt++) {
        #pragma unroll
        for (int r = 0; r < 4; r++) {
            int row = m0 + grp + (r & 1) * 8;
            int col = kt * 16 + 2 * q + (r >> 1) * 8;
            float f0 = __ldg(W_hh + (size_t)row * HH + col);
            float f1 = __ldg(W_hh + (size_t)row * HH + col + 1);
            whi0[kt][r] = f16_pack(f0, f1);
            float g0 = __ldg(W_hh + (size_t)(row + 16) * HH + col);
            float g1 = __ldg(W_hh + (size_t)(row + 16) * HH + col + 1);
            whi1[kt][r] = f16_pack(g0, g1);
        }
    }
    // h0 = 0
    for (int idx = tid; idx < 8 * 136; idx += GRUT) {
        hbw[idx] = 0u;
    }

    // ---- gate-role setup (threads 0..255) ----
    const bool is_gate = (tid < 256);
    const int gb = (tid >> 6) & 3;           // batch 0..3
    const int jp = tid & 63;
    const int j = 2 * jp;
    const int ktj = jp >> 3, uj = jp & 7;
    const int slot = (uj < 4) ? (2 * (ktj * 8 + uj)) : (2 * (ktj * 8 + (uj - 4)) + 1);
    const int hi_word = gb * 136 + slot;
    const int lo_word = (gb + 4) * 136 + slot;

    float br0 = 0.f, br1 = 0.f, bz0 = 0.f, bz1 = 0.f, bn0 = 0.f, bn1 = 0.f;
    float bhn0 = 0.f, bhn1 = 0.f;
    float hj = 0.0f, hj1 = 0.0f;
    const float* gxp = g_gx + ((size_t)(b0 + gb) * TT) * GG + j;
    float2 cr = make_float2(0.f, 0.f), cz = cr, cn = cr;
    if (is_gate) {
        br0 = __ldg(b_ih + j)          + __ldg(b_hh + j);
        br1 = __ldg(b_ih + j + 1)      + __ldg(b_hh + j + 1);
        bz0 = __ldg(b_ih + HH + j)     + __ldg(b_hh + HH + j);
        bz1 = __ldg(b_ih + HH + j + 1) + __ldg(b_hh + HH + j + 1);
        bn0 = __ldg(b_ih + 2 * HH + j);     bhn0 = __ldg(b_hh + 2 * HH + j);
        bn1 = __ldg(b_ih + 2 * HH + j + 1); bhn1 = __ldg(b_hh + 2 * HH + j + 1);
        cr = __ldg((const float2*)(gxp));
        cz = __ldg((const float2*)(gxp + HH));
        cn = __ldg((const float2*)(gxp + 2 * HH));
    }
    __syncthreads();

    const unsigned long long* hb64 = (const unsigned long long*)hbw;

    for (int t = 0; t < TT; t++) {
        // prefetch next step's gx (in flight during mma phase)
        float2 nr, nz, nn;
        float pr0, pr1, pz0, pz1, pn0, pn1;
        if (is_gate) {
            const size_t tn = (t + 1 < TT) ? (size_t)(t + 1) : (size_t)t;
            const float* pn = gxp + tn * GG;
            nr = __ldg((const float2*)(pn));
            nz = __ldg((const float2*)(pn + HH));
            nn = __ldg((const float2*)(pn + 2 * HH));
            pr0 = cr.x + br0; pr1 = cr.y + br1;
            pz0 = cz.x + bz0; pz1 = cz.y + bz1;
            pn0 = cn.x + bn0; pn1 = cn.y + bn1;
        }

        // ---- mma: 2 m-tiles x 8 kt, single fp16 term, split chains ----
        {
            float C0a[4] = {0.f, 0.f, 0.f, 0.f};
            float C0b[4] = {0.f, 0.f, 0.f, 0.f};
            float C1a[4] = {0.f, 0.f, 0.f, 0.f};
            float C1b[4] = {0.f, 0.f, 0.f, 0.f};
            #pragma unroll
            for (int kt = 0; kt < 8; kt += 2) {
                unsigned long long ba  = hb64[grp * 68 + kt * 8 + q];
                unsigned long long bbv = hb64[grp * 68 + (kt + 1) * 8 + q];
                uint32_t a0 = (uint32_t)ba,  a1 = (uint32_t)(ba >> 32);
                uint32_t c0 = (uint32_t)bbv, c1 = (uint32_t)(bbv >> 32);
                mma16816h(C0a, whi0[kt][0],   whi0[kt][1],   whi0[kt][2],   whi0[kt][3],   a0, a1);
                mma16816h(C0b, whi0[kt+1][0], whi0[kt+1][1], whi0[kt+1][2], whi0[kt+1][3], c0, c1);
                mma16816h(C1a, whi1[kt][0],   whi1[kt][1],   whi1[kt][2],   whi1[kt][3],   a0, a1);
                mma16816h(C1b, whi1[kt+1][0], whi1[kt+1][1], whi1[kt+1][2], whi1[kt+1][3], c0, c1);
            }
            ghs[(2 * q)     * 388 + m0 + grp]          = C0a[0] + C0b[0];
            ghs[(2 * q + 1) * 388 + m0 + grp]          = C0a[1] + C0b[1];
            ghs[(2 * q)     * 388 + m0 + grp + 8]      = C0a[2] + C0b[2];
            ghs[(2 * q + 1) * 388 + m0 + grp + 8]      = C0a[3] + C0b[3];
            ghs[(2 * q)     * 388 + m0 + 16 + grp]     = C1a[0] + C1b[0];
            ghs[(2 * q + 1) * 388 + m0 + 16 + grp]     = C1a[1] + C1b[1];
            ghs[(2 * q)     * 388 + m0 + 16 + grp + 8] = C1a[2] + C1b[2];
            ghs[(2 * q + 1) * 388 + m0 + 16 + grp + 8] = C1a[3] + C1b[3];
        }
        __syncthreads();

        // ---- gates: gh = col[gb] + col[gb+4] ----
        if (is_gate) {
            const float* gA = &ghs[gb * 388];
            const float* gB = &ghs[(gb + 4) * 388];
            float2 ra = *(const float2*)(gA + j);
            float2 rb = *(const float2*)(gB + j);
            float2 za = *(const float2*)(gA + HH + j);
            float2 zb = *(const float2*)(gB + HH + j);
            float2 na = *(const float2*)(gA + 2 * HH + j);
            float2 nb = *(const float2*)(gB + 2 * HH + j);
            float r0 = sig_t(pr0 + ra.x + rb.x);
            float r1 = sig_t(pr1 + ra.y + rb.y);
            float z0 = sig_t(pz0 + za.x + zb.x);
            float z1 = sig_t(pz1 + za.y + zb.y);
            float n0 = fast_tanh(pn0 + r0 * (na.x + nb.x + bhn0));
            float n1 = fast_tanh(pn1 + r1 * (na.y + nb.y + bhn1));
            hj  = fmaf(z0, hj - n0, n0);
            hj1 = fmaf(z1, hj1 - n1, n1);
            hbw[hi_word] = f16_pack(hj, hj1);
            hbw[lo_word] = f16_lo_pack(hj, hj1);
            cr = nr; cz = nz; cn = nn;
        }
        __syncthreads();
    }

    if (is_gate) {
        *(float2*)(out + (size_t)(b0 + gb) * HH + j) = make_float2(hj, hj1);
    }
}

// ================= launch =================
extern "C" void kernel_launch(void* const* d_in, const int* in_sizes, int n_in,
                              void* d_out, int out_size)
{
    const float* x    = (const float*)d_in[0];
    const float* W_ih = (const float*)d_in[1];
    const float* W_hh = (const float*)d_in[2];
    const float* b_ih = (const float*)d_in[3];
    const float* b_hh = (const float*)d_in[4];
    float* out = (float*)d_out;

    cudaFuncSetAttribute(gx_hmma_kernel,
                         cudaFuncAttributeMaxDynamicSharedMemorySize, GX_SMEM);

    gx_hmma_kernel<<<dim3(16, BB), GXT, GX_SMEM>>>(x, W_ih);
    gru_hmma_kernel<<<BB / 4, GRUT>>>(W_hh, b_ih, b_hh, out);
}

// round 15
// speedup vs baseline: 1.3348x; 1.0224x over previous
#include <cuda_runtime.h>
#include <cuda_bf16.h>
#include <cuda_fp16.h>
#include <cstdint>

#define BB 256
#define MM 80
#define TT 1000
#define HH 128
#define GG 384
#define TPAD 1024

// ---------------- device scratch ----------------
__device__ float g_gx[(size_t)BB * TT * GG];                // 393 MB
__device__ __nv_bfloat16 g_xhi[(size_t)BB * TPAD * MM];     // 42 MB
__device__ __nv_bfloat16 g_xlo[(size_t)BB * TPAD * MM];     // 42 MB

// ---------------- helpers ----------------
__device__ __forceinline__ float fast_tanh(float x) {
    float ax = fabsf(x);
    float e = __expf(-2.0f * ax);
    float t = __fdividef(1.0f - e, 1.0f + e);
    return copysignf(t, x);
}
// sigmoid via single-instruction tanh.approx: sig(x) = 0.5*tanh(0.5x) + 0.5
__device__ __forceinline__ float sig_t(float x) {
    float t;
    asm("tanh.approx.f32 %0, %1;" : "=f"(t) : "f"(0.5f * x));
    return fmaf(0.5f, t, 0.5f);
}
__device__ __forceinline__ void cp16(uint32_t saddr, const void* g) {
    asm volatile("cp.async.cg.shared.global [%0], [%1], 16;" :: "r"(saddr), "l"(g));
}
__device__ __forceinline__ void cp_commit() { asm volatile("cp.async.commit_group;" ::: "memory"); }
__device__ __forceinline__ void cp_wait0()  { asm volatile("cp.async.wait_group 0;" ::: "memory"); }
__device__ __forceinline__ uint32_t smem_u32(const void* p) {
    uint32_t a;
    asm("{ .reg .u64 t; cvta.to.shared.u64 t, %1; cvt.u32.u64 %0, t; }" : "=r"(a) : "l"(p));
    return a;
}
// bf16 mma (gx kernel)
__device__ __forceinline__ void mma16816(float* c, uint32_t a0, uint32_t a1,
                                         uint32_t a2, uint32_t a3,
                                         uint32_t b0, uint32_t b1) {
    asm("mma.sync.aligned.m16n8k16.row.col.f32.bf16.bf16.f32 "
        "{%0,%1,%2,%3}, {%4,%5,%6,%7}, {%8,%9}, {%0,%1,%2,%3};"
        : "+f"(c[0]), "+f"(c[1]), "+f"(c[2]), "+f"(c[3])
        : "r"(a0), "r"(a1), "r"(a2), "r"(a3), "r"(b0), "r"(b1));
}
// fp16 mma (gru kernel)
__device__ __forceinline__ void mma16816h(float* c, uint32_t a0, uint32_t a1,
                                          uint32_t a2, uint32_t a3,
                                          uint32_t b0, uint32_t b1) {
    asm("mma.sync.aligned.m16n8k16.row.col.f32.f16.f16.f32 "
        "{%0,%1,%2,%3}, {%4,%5,%6,%7}, {%8,%9}, {%0,%1,%2,%3};"
        : "+f"(c[0]), "+f"(c[1]), "+f"(c[2]), "+f"(c[3])
        : "r"(a0), "r"(a1), "r"(a2), "r"(a3), "r"(b0), "r"(b1));
}
__device__ __forceinline__ uint32_t f16_pack(float a, float b) {
    __half2 p = __floats2half2_rn(a, b);
    return reinterpret_cast<uint32_t&>(p);
}
__device__ __forceinline__ uint32_t f16_lo_pack(float a, float b) {
    float ra = a - __half2float(__float2half_rn(a));
    float rb = b - __half2float(__float2half_rn(b));
    return f16_pack(ra, rb);
}

// ================= prep: transpose + bf16 split =================
#define PREP_THREADS 256
__global__ __launch_bounds__(PREP_THREADS)
void prep_kernel(const float* __restrict__ x)
{
    __shared__ float xs[MM][129];
    const int b = blockIdx.y, t0 = blockIdx.x * 128;
    const int tid = threadIdx.x;

    for (int idx = tid; idx < MM * 128; idx += PREP_THREADS) {
        int m = idx >> 7, j = idx & 127;
        int t = t0 + j;
        xs[m][j] = (t < TT) ? x[((size_t)b * MM + m) * TT + t] : 0.0f;
    }
    __syncthreads();

    for (int idx = tid; idx < 128 * 10; idx += PREP_THREADS) {
        int j = idx / 10, mv = idx % 10;
        int m0 = mv * 8;
        __align__(16) __nv_bfloat16 hi[8];
        __align__(16) __nv_bfloat16 lo[8];
        #pragma unroll
        for (int u = 0; u < 8; u++) {
            float v = xs[m0 + u][j];
            __nv_bfloat16 h = __float2bfloat16(v);
            hi[u] = h;
            lo[u] = __float2bfloat16(v - __bfloat162float(h));
        }
        size_t off = ((size_t)b * TPAD + t0 + j) * MM + m0;
        *(uint4*)(g_xhi + off) = *(const uint4*)hi;
        *(uint4*)(g_xlo + off) = *(const uint4*)lo;
    }
}

// ================= gx via mma.sync HMMA (split-bf16, 3 terms) =================
#define GXT 256
#define A_PITCH 88
#define W_PITCH 84
#define SM_AHI 0
#define SM_ALO (128 * A_PITCH * 2)
#define SM_WHI (SM_ALO + 128 * A_PITCH * 2)
#define SM_WLO (SM_WHI + 192 * W_PITCH * 2)
#define GX_SMEM (SM_WLO + 192 * W_PITCH * 2)

__device__ __forceinline__ uint32_t lds_pair(const char* base, int row, int col, int pitch) {
    return *(const uint32_t*)(base + (size_t)(row * pitch + col) * 2);
}

__global__ __launch_bounds__(GXT)
void gx_hmma_kernel(const float* __restrict__ W_ih)
{
    extern __shared__ char sm[];
    const int tid = threadIdx.x;
    const int lane = tid & 31;
    const int w = tid >> 5;
    const int grp = lane >> 2;
    const int q = lane & 3;
    const int tt = blockIdx.x >> 1;
    const int ghalf = blockIdx.x & 1;
    const int gbase = ghalf * 192;
    const int b = blockIdx.y;
    const uint32_t sb = smem_u32(sm);

    for (int i = tid; i < 2560; i += GXT) {
        int split = i / 1280;
        int rem = i - split * 1280;
        int row = rem / 10, ch = rem - row * 10;
        uint32_t dst = sb + (split ? SM_ALO : SM_AHI) + row * (A_PITCH * 2) + ch * 16;
        const __nv_bfloat16* src = (split ? g_xlo : g_xhi)
            + ((size_t)b * TPAD + tt * 128 + row) * MM + ch * 8;
        cp16(dst, src);
    }
    cp_commit();

    for (int i = tid; i < 192 * MM; i += GXT) {
        int g = i / MM, m = i - g * MM;
        float v = W_ih[(size_t)(gbase + g) * MM + m];
        __nv_bfloat16 h = __float2bfloat16(v);
        __nv_bfloat16 l = __float2bfloat16(v - __bfloat162float(h));
        *(__nv_bfloat16*)(sm + SM_WHI + (size_t)(g * W_PITCH + m) * 2) = h;
        *(__nv_bfloat16*)(sm + SM_WLO + (size_t)(g * W_PITCH + m) * 2) = l;
    }
    cp_wait0();
    __syncthreads();

    const int r0 = w * 16 + grp;
    uint32_t ahi[20], alo[20];
    #pragma unroll
    for (int ks = 0; ks < 5; ks++) {
        int c = 16 * ks + 2 * q;
        ahi[4 * ks + 0] = lds_pair(sm + SM_AHI, r0,     c,     A_PITCH);
        ahi[4 * ks + 1] = lds_pair(sm + SM_AHI, r0 + 8, c,     A_PITCH);
        ahi[4 * ks + 2] = lds_pair(sm + SM_AHI, r0,     c + 8, A_PITCH);
        ahi[4 * ks + 3] = lds_pair(sm + SM_AHI, r0 + 8, c + 8, A_PITCH);
        alo[4 * ks + 0] = lds_pair(sm + SM_ALO, r0,     c,     A_PITCH);
        alo[4 * ks + 1] = lds_pair(sm + SM_ALO, r0 + 8, c,     A_PITCH);
        alo[4 * ks + 2] = lds_pair(sm + SM_ALO, r0,     c + 8, A_PITCH);
        alo[4 * ks + 3] = lds_pair(sm + SM_ALO, r0 + 8, c + 8, A_PITCH);
    }

    const int trow = tt * 128 + w * 16 + grp;
    float* dst = g_gx + ((size_t)b * TT + trow) * GG + gbase;
    float* dst8 = dst + 8 * GG;
    const bool v0 = (trow < TT);
    const bool v8 = (trow + 8 < TT);

    for (int gp = 0; gp < 12; gp++) {
        float acc0[4] = {0.f, 0.f, 0.f, 0.f};
        float acc1[4] = {0.f, 0.f, 0.f, 0.f};
        const int gA = gp * 16 + grp;
        const int gB = gp * 16 + 8 + grp;
        #pragma unroll
        for (int ks = 0; ks < 5; ks++) {
            int c = 16 * ks + 2 * q;
            uint32_t bh0a = lds_pair(sm + SM_WHI, gA, c,     W_PITCH);
            uint32_t bh0b = lds_pair(sm + SM_WHI, gA, c + 8, W_PITCH);
            uint32_t bh1a = lds_pair(sm + SM_WHI, gB, c,     W_PITCH);
            uint32_t bh1b = lds_pair(sm + SM_WHI, gB, c + 8, W_PITCH);
            mma16816(acc0, ahi[4*ks], ahi[4*ks+1], ahi[4*ks+2], ahi[4*ks+3], bh0a, bh0b);
            mma16816(acc1, ahi[4*ks], ahi[4*ks+1], ahi[4*ks+2], ahi[4*ks+3], bh1a, bh1b);
            mma16816(acc0, alo[4*ks], alo[4*ks+1], alo[4*ks+2], alo[4*ks+3], bh0a, bh0b);
            mma16816(acc1, alo[4*ks], alo[4*ks+1], alo[4*ks+2], alo[4*ks+3], bh1a, bh1b);
            uint32_t bl0a = lds_pair(sm + SM_WLO, gA, c,     W_PITCH);
            uint32_t bl0b = lds_pair(sm + SM_WLO, gA, c + 8, W_PITCH);
            uint32_t bl1a = lds_pair(sm + SM_WLO, gB, c,     W_PITCH);
            uint32_t bl1b = lds_pair(sm + SM_WLO, gB, c + 8, W_PITCH);
            mma16816(acc0, ahi[4*ks], ahi[4*ks+1], ahi[4*ks+2], ahi[4*ks+3], bl0a, bl0b);
            mma16816(acc1, ahi[4*ks], ahi[4*ks+1], ahi[4*ks+2], ahi[4*ks+3], bl1a, bl1b);
        }
        const int col0 = gp * 16 + 2 * q;
        if (v0) {
            *(float2*)(dst + col0)     = make_float2(acc0[0], acc0[1]);
            *(float2*)(dst + col0 + 8) = make_float2(acc1[0], acc1[1]);
        }
        if (v8) {
            *(float2*)(dst8 + col0)     = make_float2(acc0[2], acc0[3]);
            *(float2*)(dst8 + col0 + 8) = make_float2(acc1[2], acc1[3]);
        }
    }
}

// ================= gru: 4-batch fp16 HMMA (R9 shape + approx sigmoids) ========
// 64 blocks x 384 threads (12 warps). Warp w owns m-tiles 2w, 2w+1.
// W fp16 fragments register-resident. n=8 B cols = [h_hi b0..3 | h_lo b0..3].
// gh = col[b] + col[b+4]. Gates: threads 0..255 (batch = tid>>6, j-pair = tid&63).
#define GRUT 384

__global__ __launch_bounds__(GRUT, 1)
void gru_hmma_kernel(const float* __restrict__ W_hh,
                     const float* __restrict__ b_ih,
                     const float* __restrict__ b_hh,
                     float* __restrict__ out)
{
    __shared__ uint32_t hbw[8 * 136];        // u64[8][68] view (B fragments)
    __shared__ float ghs[8 * 388];

    const int tid = threadIdx.x;
    const int lane = tid & 31;
    const int wid = tid >> 5;
    const int grp = lane >> 2;
    const int q = lane & 3;
    const int b0 = blockIdx.x * 4;
    const int m0 = wid * 32;                 // rows for this warp's two m-tiles

    // ---- W fragments (fp16), both m-tiles in registers ----
    uint32_t whi0[8][4], whi1[8][4];
    #pragma unroll
    for (int kt = 0; kt < 8; kt++) {
        #pragma unroll
        for (int r = 0; r < 4; r++) {
            int row = m0 + grp + (r & 1) * 8;
            int col = kt * 16 + 2 * q + (r >> 1) * 8;
            float f0 = __ldg(W_hh + (size_t)row * HH + col);
            float f1 = __ldg(W_hh + (size_t)row * HH + col + 1);
            whi0[kt][r] = f16_pack(f0, f1);
            float g0 = __ldg(W_hh + (size_t)(row + 16) * HH + col);
            float g1 = __ldg(W_hh + (size_t)(row + 16) * HH + col + 1);
            whi1[kt][r] = f16_pack(g0, g1);
        }
    }
    // h0 = 0
    for (int idx = tid; idx < 8 * 136; idx += GRUT) {
        hbw[idx] = 0u;
    }

    // ---- gate-role setup (threads 0..255) ----
    const bool is_gate = (tid < 256);
    const int gb = (tid >> 6) & 3;           // batch 0..3
    const int jp = tid & 63;
    const int j = 2 * jp;
    const int ktj = jp >> 3, uj = jp & 7;
    const int slot = (uj < 4) ? (2 * (ktj * 8 + uj)) : (2 * (ktj * 8 + (uj - 4)) + 1);
    const int hi_word = gb * 136 + slot;
    const int lo_word = (gb + 4) * 136 + slot;

    float br0 = 0.f, br1 = 0.f, bz0 = 0.f, bz1 = 0.f, bn0 = 0.f, bn1 = 0.f;
    float bhn0 = 0.f, bhn1 = 0.f;
    float hj = 0.0f, hj1 = 0.0f;
    const float* gxp = g_gx + ((size_t)(b0 + gb) * TT) * GG + j;
    float2 cr = make_float2(0.f, 0.f), cz = cr, cn = cr;
    if (is_gate) {
        br0 = __ldg(b_ih + j)          + __ldg(b_hh + j);
        br1 = __ldg(b_ih + j + 1)      + __ldg(b_hh + j + 1);
        bz0 = __ldg(b_ih + HH + j)     + __ldg(b_hh + HH + j);
        bz1 = __ldg(b_ih + HH + j + 1) + __ldg(b_hh + HH + j + 1);
        bn0 = __ldg(b_ih + 2 * HH + j);     bhn0 = __ldg(b_hh + 2 * HH + j);
        bn1 = __ldg(b_ih + 2 * HH + j + 1); bhn1 = __ldg(b_hh + 2 * HH + j + 1);
        cr = __ldg((const float2*)(gxp));
        cz = __ldg((const float2*)(gxp + HH));
        cn = __ldg((const float2*)(gxp + 2 * HH));
    }
    __syncthreads();

    const unsigned long long* hb64 = (const unsigned long long*)hbw;

    for (int t = 0; t < TT; t++) {
        // prefetch next step's gx (in flight during mma phase)
        float2 nr, nz, nn;
        float pr0, pr1, pz0, pz1, pn0, pn1;
        if (is_gate) {
            const size_t tn = (t + 1 < TT) ? (size_t)(t + 1) : (size_t)t;
            const float* pn = gxp + tn * GG;
            nr = __ldg((const float2*)(pn));
            nz = __ldg((const float2*)(pn + HH));
            nn = __ldg((const float2*)(pn + 2 * HH));
            pr0 = cr.x + br0; pr1 = cr.y + br1;
            pz0 = cz.x + bz0; pz1 = cz.y + bz1;
            pn0 = cn.x + bn0; pn1 = cn.y + bn1;
        }

        // ---- mma: 2 m-tiles x 8 kt, single fp16 term, split chains ----
        {
            float C0a[4] = {0.f, 0.f, 0.f, 0.f};
            float C0b[4] = {0.f, 0.f, 0.f, 0.f};
            float C1a[4] = {0.f, 0.f, 0.f, 0.f};
            float C1b[4] = {0.f, 0.f, 0.f, 0.f};
            #pragma unroll
            for (int kt = 0; kt < 8; kt += 2) {
                unsigned long long ba  = hb64[grp * 68 + kt * 8 + q];
                unsigned long long bbv = hb64[grp * 68 + (kt + 1) * 8 + q];
                uint32_t a0 = (uint32_t)ba,  a1 = (uint32_t)(ba >> 32);
                uint32_t c0 = (uint32_t)bbv, c1 = (uint32_t)(bbv >> 32);
                mma16816h(C0a, whi0[kt][0],   whi0[kt][1],   whi0[kt][2],   whi0[kt][3],   a0, a1);
                mma16816h(C0b, whi0[kt+1][0], whi0[kt+1][1], whi0[kt+1][2], whi0[kt+1][3], c0, c1);
                mma16816h(C1a, whi1[kt][0],   whi1[kt][1],   whi1[kt][2],   whi1[kt][3],   a0, a1);
                mma16816h(C1b, whi1[kt+1][0], whi1[kt+1][1], whi1[kt+1][2], whi1[kt+1][3], c0, c1);
            }
            ghs[(2 * q)     * 388 + m0 + grp]          = C0a[0] + C0b[0];
            ghs[(2 * q + 1) * 388 + m0 + grp]          = C0a[1] + C0b[1];
            ghs[(2 * q)     * 388 + m0 + grp + 8]      = C0a[2] + C0b[2];
            ghs[(2 * q + 1) * 388 + m0 + grp + 8]      = C0a[3] + C0b[3];
            ghs[(2 * q)     * 388 + m0 + 16 + grp]     = C1a[0] + C1b[0];
            ghs[(2 * q + 1) * 388 + m0 + 16 + grp]     = C1a[1] + C1b[1];
            ghs[(2 * q)     * 388 + m0 + 16 + grp + 8] = C1a[2] + C1b[2];
            ghs[(2 * q + 1) * 388 + m0 + 16 + grp + 8] = C1a[3] + C1b[3];
        }
        __syncthreads();

        // ---- gates: gh = col[gb] + col[gb+4] ----
        if (is_gate) {
            const float* gA = &ghs[gb * 388];
            const float* gB = &ghs[(gb + 4) * 388];
            float2 ra = *(const float2*)(gA + j);
            float2 rb = *(const float2*)(gB + j);
            float2 za = *(const float2*)(gA + HH + j);
            float2 zb = *(const float2*)(gB + HH + j);
            float2 na = *(const float2*)(gA + 2 * HH + j);
            float2 nb = *(const float2*)(gB + 2 * HH + j);
            float r0 = sig_t(pr0 + ra.x + rb.x);
            float r1 = sig_t(pr1 + ra.y + rb.y);
            float z0 = sig_t(pz0 + za.x + zb.x);
            float z1 = sig_t(pz1 + za.y + zb.y);
            float n0 = fast_tanh(pn0 + r0 * (na.x + nb.x + bhn0));
            float n1 = fast_tanh(pn1 + r1 * (na.y + nb.y + bhn1));
            hj  = fmaf(z0, hj - n0, n0);
            hj1 = fmaf(z1, hj1 - n1, n1);
            hbw[hi_word] = f16_pack(hj, hj1);
            hbw[lo_word] = f16_lo_pack(hj, hj1);
            cr = nr; cz = nz; cn = nn;
        }
        __syncthreads();
    }

    if (is_gate) {
        *(float2*)(out + (size_t)(b0 + gb) * HH + j) = make_float2(hj, hj1);
    }
}

// ================= launch =================
extern "C" void kernel_launch(void* const* d_in, const int* in_sizes, int n_in,
                              void* d_out, int out_size)
{
    const float* x    = (const float*)d_in[0];
    const float* W_ih = (const float*)d_in[1];
    const float* W_hh = (const float*)d_in[2];
    const float* b_ih = (const float*)d_in[3];
    const float* b_hh = (const float*)d_in[4];
    float* out = (float*)d_out;

    cudaFuncSetAttribute(gx_hmma_kernel,
                         cudaFuncAttributeMaxDynamicSharedMemorySize, GX_SMEM);

    prep_kernel<<<dim3(8, BB), PREP_THREADS>>>(x);
    gx_hmma_kernel<<<dim3(16, BB), GXT, GX_SMEM>>>(W_ih);
    gru_hmma_kernel<<<BB / 4, GRUT>>>(W_hh, b_ih, b_hh, out);
}

// round 16
// speedup vs baseline: 1.3400x; 1.0039x over previous
#include <cuda_runtime.h>
#include <cuda_bf16.h>
#include <cuda_fp16.h>
#include <cstdint>

#define BB 256
#define MM 80
#define TT 1000
#define HH 128
#define GG 384
#define TPAD 1024

// ---------------- device scratch ----------------
__device__ float g_gx[(size_t)BB * TT * GG];                // 393 MB
__device__ __nv_bfloat16 g_xhi[(size_t)BB * TPAD * MM];     // 42 MB
__device__ __nv_bfloat16 g_xlo[(size_t)BB * TPAD * MM];     // 42 MB

// ---------------- helpers ----------------
__device__ __forceinline__ float fast_tanh(float x) {
    float ax = fabsf(x);
    float e = __expf(-2.0f * ax);
    float t = __fdividef(1.0f - e, 1.0f + e);
    return copysignf(t, x);
}
// sigmoid via single-instruction tanh.approx: sig(x) = 0.5*tanh(0.5x) + 0.5
__device__ __forceinline__ float sig_t(float x) {
    float t;
    asm("tanh.approx.f32 %0, %1;" : "=f"(t) : "f"(0.5f * x));
    return fmaf(0.5f, t, 0.5f);
}
__device__ __forceinline__ void cp16(uint32_t saddr, const void* g) {
    asm volatile("cp.async.cg.shared.global [%0], [%1], 16;" :: "r"(saddr), "l"(g));
}
__device__ __forceinline__ void cp_commit() { asm volatile("cp.async.commit_group;" ::: "memory"); }
__device__ __forceinline__ void cp_wait0()  { asm volatile("cp.async.wait_group 0;" ::: "memory"); }
__device__ __forceinline__ uint32_t smem_u32(const void* p) {
    uint32_t a;
    asm("{ .reg .u64 t; cvta.to.shared.u64 t, %1; cvt.u32.u64 %0, t; }" : "=r"(a) : "l"(p));
    return a;
}
// bf16 mma (gx kernel)
__device__ __forceinline__ void mma16816(float* c, uint32_t a0, uint32_t a1,
                                         uint32_t a2, uint32_t a3,
                                         uint32_t b0, uint32_t b1) {
    asm("mma.sync.aligned.m16n8k16.row.col.f32.bf16.bf16.f32 "
        "{%0,%1,%2,%3}, {%4,%5,%6,%7}, {%8,%9}, {%0,%1,%2,%3};"
        : "+f"(c[0]), "+f"(c[1]), "+f"(c[2]), "+f"(c[3])
        : "r"(a0), "r"(a1), "r"(a2), "r"(a3), "r"(b0), "r"(b1));
}
// fp16 mma (gru kernel)
__device__ __forceinline__ void mma16816h(float* c, uint32_t a0, uint32_t a1,
                                          uint32_t a2, uint32_t a3,
                                          uint32_t b0, uint32_t b1) {
    asm("mma.sync.aligned.m16n8k16.row.col.f32.f16.f16.f32 "
        "{%0,%1,%2,%3}, {%4,%5,%6,%7}, {%8,%9}, {%0,%1,%2,%3};"
        : "+f"(c[0]), "+f"(c[1]), "+f"(c[2]), "+f"(c[3])
        : "r"(a0), "r"(a1), "r"(a2), "r"(a3), "r"(b0), "r"(b1));
}
__device__ __forceinline__ uint32_t f16_pack(float a, float b) {
    __half2 p = __floats2half2_rn(a, b);
    return reinterpret_cast<uint32_t&>(p);
}
__device__ __forceinline__ uint32_t f16_lo_pack(float a, float b) {
    float ra = a - __half2float(__float2half_rn(a));
    float rb = b - __half2float(__float2half_rn(b));
    return f16_pack(ra, rb);
}

// ================= prep: transpose + bf16 split =================
#define PREP_THREADS 256
__global__ __launch_bounds__(PREP_THREADS)
void prep_kernel(const float* __restrict__ x)
{
    __shared__ float xs[MM][129];
    const int b = blockIdx.y, t0 = blockIdx.x * 128;
    const int tid = threadIdx.x;

    for (int idx = tid; idx < MM * 128; idx += PREP_THREADS) {
        int m = idx >> 7, j = idx & 127;
        int t = t0 + j;
        xs[m][j] = (t < TT) ? x[((size_t)b * MM + m) * TT + t] : 0.0f;
    }
    __syncthreads();

    for (int idx = tid; idx < 128 * 10; idx += PREP_THREADS) {
        int j = idx / 10, mv = idx % 10;
        int m0 = mv * 8;
        __align__(16) __nv_bfloat16 hi[8];
        __align__(16) __nv_bfloat16 lo[8];
        #pragma unroll
        for (int u = 0; u < 8; u++) {
            float v = xs[m0 + u][j];
            __nv_bfloat16 h = __float2bfloat16(v);
            hi[u] = h;
            lo[u] = __float2bfloat16(v - __bfloat162float(h));
        }
        size_t off = ((size_t)b * TPAD + t0 + j) * MM + m0;
        *(uint4*)(g_xhi + off) = *(const uint4*)hi;
        *(uint4*)(g_xlo + off) = *(const uint4*)lo;
    }
}

// ================= gx via mma.sync HMMA (split-bf16, 3 terms) =================
#define GXT 256
#define A_PITCH 88
#define W_PITCH 84
#define SM_AHI 0
#define SM_ALO (128 * A_PITCH * 2)
#define SM_WHI (SM_ALO + 128 * A_PITCH * 2)
#define SM_WLO (SM_WHI + 192 * W_PITCH * 2)
#define GX_SMEM (SM_WLO + 192 * W_PITCH * 2)

__device__ __forceinline__ uint32_t lds_pair(const char* base, int row, int col, int pitch) {
    return *(const uint32_t*)(base + (size_t)(row * pitch + col) * 2);
}

__global__ __launch_bounds__(GXT)
void gx_hmma_kernel(const float* __restrict__ W_ih)
{
    extern __shared__ char sm[];
    const int tid = threadIdx.x;
    const int lane = tid & 31;
    const int w = tid >> 5;
    const int grp = lane >> 2;
    const int q = lane & 3;
    const int tt = blockIdx.x >> 1;
    const int ghalf = blockIdx.x & 1;
    const int gbase = ghalf * 192;
    const int b = blockIdx.y;
    const uint32_t sb = smem_u32(sm);

    for (int i = tid; i < 2560; i += GXT) {
        int split = i / 1280;
        int rem = i - split * 1280;
        int row = rem / 10, ch = rem - row * 10;
        uint32_t dst = sb + (split ? SM_ALO : SM_AHI) + row * (A_PITCH * 2) + ch * 16;
        const __nv_bfloat16* src = (split ? g_xlo : g_xhi)
            + ((size_t)b * TPAD + tt * 128 + row) * MM + ch * 8;
        cp16(dst, src);
    }
    cp_commit();

    for (int i = tid; i < 192 * MM; i += GXT) {
        int g = i / MM, m = i - g * MM;
        float v = W_ih[(size_t)(gbase + g) * MM + m];
        __nv_bfloat16 h = __float2bfloat16(v);
        __nv_bfloat16 l = __float2bfloat16(v - __bfloat162float(h));
        *(__nv_bfloat16*)(sm + SM_WHI + (size_t)(g * W_PITCH + m) * 2) = h;
        *(__nv_bfloat16*)(sm + SM_WLO + (size_t)(g * W_PITCH + m) * 2) = l;
    }
    cp_wait0();
    __syncthreads();

    const int r0 = w * 16 + grp;
    uint32_t ahi[20], alo[20];
    #pragma unroll
    for (int ks = 0; ks < 5; ks++) {
        int c = 16 * ks + 2 * q;
        ahi[4 * ks + 0] = lds_pair(sm + SM_AHI, r0,     c,     A_PITCH);
        ahi[4 * ks + 1] = lds_pair(sm + SM_AHI, r0 + 8, c,     A_PITCH);
        ahi[4 * ks + 2] = lds_pair(sm + SM_AHI, r0,     c + 8, A_PITCH);
        ahi[4 * ks + 3] = lds_pair(sm + SM_AHI, r0 + 8, c + 8, A_PITCH);
        alo[4 * ks + 0] = lds_pair(sm + SM_ALO, r0,     c,     A_PITCH);
        alo[4 * ks + 1] = lds_pair(sm + SM_ALO, r0 + 8, c,     A_PITCH);
        alo[4 * ks + 2] = lds_pair(sm + SM_ALO, r0,     c + 8, A_PITCH);
        alo[4 * ks + 3] = lds_pair(sm + SM_ALO, r0 + 8, c + 8, A_PITCH);
    }

    const int trow = tt * 128 + w * 16 + grp;
    float* dst = g_gx + ((size_t)b * TT + trow) * GG + gbase;
    float* dst8 = dst + 8 * GG;
    const bool v0 = (trow < TT);
    const bool v8 = (trow + 8 < TT);

    for (int gp = 0; gp < 12; gp++) {
        float acc0[4] = {0.f, 0.f, 0.f, 0.f};
        float acc1[4] = {0.f, 0.f, 0.f, 0.f};
        const int gA = gp * 16 + grp;
        const int gB = gp * 16 + 8 + grp;
        #pragma unroll
        for (int ks = 0; ks < 5; ks++) {
            int c = 16 * ks + 2 * q;
            uint32_t bh0a = lds_pair(sm + SM_WHI, gA, c,     W_PITCH);
            uint32_t bh0b = lds_pair(sm + SM_WHI, gA, c + 8, W_PITCH);
            uint32_t bh1a = lds_pair(sm + SM_WHI, gB, c,     W_PITCH);
            uint32_t bh1b = lds_pair(sm + SM_WHI, gB, c + 8, W_PITCH);
            mma16816(acc0, ahi[4*ks], ahi[4*ks+1], ahi[4*ks+2], ahi[4*ks+3], bh0a, bh0b);
            mma16816(acc1, ahi[4*ks], ahi[4*ks+1], ahi[4*ks+2], ahi[4*ks+3], bh1a, bh1b);
            mma16816(acc0, alo[4*ks], alo[4*ks+1], alo[4*ks+2], alo[4*ks+3], bh0a, bh0b);
            mma16816(acc1, alo[4*ks], alo[4*ks+1], alo[4*ks+2], alo[4*ks+3], bh1a, bh1b);
            uint32_t bl0a = lds_pair(sm + SM_WLO, gA, c,     W_PITCH);
            uint32_t bl0b = lds_pair(sm + SM_WLO, gA, c + 8, W_PITCH);
            uint32_t bl1a = lds_pair(sm + SM_WLO, gB, c,     W_PITCH);
            uint32_t bl1b = lds_pair(sm + SM_WLO, gB, c + 8, W_PITCH);
            mma16816(acc0, ahi[4*ks], ahi[4*ks+1], ahi[4*ks+2], ahi[4*ks+3], bl0a, bl0b);
            mma16816(acc1, ahi[4*ks], ahi[4*ks+1], ahi[4*ks+2], ahi[4*ks+3], bl1a, bl1b);
        }
        const int col0 = gp * 16 + 2 * q;
        if (v0) {
            *(float2*)(dst + col0)     = make_float2(acc0[0], acc0[1]);
            *(float2*)(dst + col0 + 8) = make_float2(acc1[0], acc1[1]);
        }
        if (v8) {
            *(float2*)(dst8 + col0)     = make_float2(acc0[2], acc0[3]);
            *(float2*)(dst8 + col0 + 8) = make_float2(acc1[2], acc1[3]);
        }
    }
}

// ================= gru: 4-batch fp16 HMMA (R9 shape + approx sigmoids) ========
// 64 blocks x 384 threads (12 warps). Warp w owns m-tiles 2w, 2w+1.
// W fp16 fragments register-resident. n=8 B cols = [h_hi b0..3 | h_lo b0..3].
// gh = col[b] + col[b+4]. Gates: threads 0..255 (batch = tid>>6, j-pair = tid&63).
#define GRUT 384

__global__ __launch_bounds__(GRUT, 1)
void gru_hmma_kernel(const float* __restrict__ W_hh,
                     const float* __restrict__ b_ih,
                     const float* __restrict__ b_hh,
                     float* __restrict__ out)
{
    __shared__ uint32_t hbw[8 * 136];        // u64[8][68] view (B fragments)
    __shared__ float ghs[8 * 388];

    const int tid = threadIdx.x;
    const int lane = tid & 31;
    const int wid = tid >> 5;
    const int grp = lane >> 2;
    const int q = lane & 3;
    const int b0 = blockIdx.x * 4;
    const int m0 = wid * 32;                 // rows for this warp's two m-tiles

    // ---- W fragments (fp16), both m-tiles in registers ----
    uint32_t whi0[8][4], whi1[8][4];
    #pragma unroll
    for (int kt = 0; kt < 8; kt++) {
        #pragma unroll
        for (int r = 0; r < 4; r++) {
            int row = m0 + grp + (r & 1) * 8;
            int col = kt * 16 + 2 * q + (r >> 1) * 8;
            float f0 = __ldg(W_hh + (size_t)row * HH + col);
            float f1 = __ldg(W_hh + (size_t)row * HH + col + 1);
            whi0[kt][r] = f16_pack(f0, f1);
            float g0 = __ldg(W_hh + (size_t)(row + 16) * HH + col);
            float g1 = __ldg(W_hh + (size_t)(row + 16) * HH + col + 1);
            whi1[kt][r] = f16_pack(g0, g1);
        }
    }
    // h0 = 0
    for (int idx = tid; idx < 8 * 136; idx += GRUT) {
        hbw[idx] = 0u;
    }

    // ---- gate-role setup (threads 0..255) ----
    const bool is_gate = (tid < 256);
    const int gb = (tid >> 6) & 3;           // batch 0..3
    const int jp = tid & 63;
    const int j = 2 * jp;
    const int ktj = jp >> 3, uj = jp & 7;
    const int slot = (uj < 4) ? (2 * (ktj * 8 + uj)) : (2 * (ktj * 8 + (uj - 4)) + 1);
    const int hi_word = gb * 136 + slot;
    const int lo_word = (gb + 4) * 136 + slot;

    float br0 = 0.f, br1 = 0.f, bz0 = 0.f, bz1 = 0.f, bn0 = 0.f, bn1 = 0.f;
    float bhn0 = 0.f, bhn1 = 0.f;
    float hj = 0.0f, hj1 = 0.0f;
    const float* gxp = g_gx + ((size_t)(b0 + gb) * TT) * GG + j;
    float2 cr = make_float2(0.f, 0.f), cz = cr, cn = cr;
    if (is_gate) {
        br0 = __ldg(b_ih + j)          + __ldg(b_hh + j);
        br1 = __ldg(b_ih + j + 1)      + __ldg(b_hh + j + 1);
        bz0 = __ldg(b_ih + HH + j)     + __ldg(b_hh + HH + j);
        bz1 = __ldg(b_ih + HH + j + 1) + __ldg(b_hh + HH + j + 1);
        bn0 = __ldg(b_ih + 2 * HH + j);     bhn0 = __ldg(b_hh + 2 * HH + j);
        bn1 = __ldg(b_ih + 2 * HH + j + 1); bhn1 = __ldg(b_hh + 2 * HH + j + 1);
        cr = __ldg((const float2*)(gxp));
        cz = __ldg((const float2*)(gxp + HH));
        cn = __ldg((const float2*)(gxp + 2 * HH));
    }
    __syncthreads();

    const unsigned long long* hb64 = (const unsigned long long*)hbw;

    for (int t = 0; t < TT; t++) {
        // prefetch next step's gx (in flight during mma phase)
        float2 nr, nz, nn;
        float pr0, pr1, pz0, pz1, pn0, pn1;
        if (is_gate) {
            const size_t tn = (t + 1 < TT) ? (size_t)(t + 1) : (size_t)t;
            const float* pn = gxp + tn * GG;
            nr = __ldg((const float2*)(pn));
            nz = __ldg((const float2*)(pn + HH));
            nn = __ldg((const float2*)(pn + 2 * HH));
            pr0 = cr.x + br0; pr1 = cr.y + br1;
            pz0 = cz.x + bz0; pz1 = cz.y + bz1;
            pn0 = cn.x + bn0; pn1 = cn.y + bn1;
        }

        // ---- mma: 2 m-tiles x 8 kt, single fp16 term, split chains ----
        {
            float C0a[4] = {0.f, 0.f, 0.f, 0.f};
            float C0b[4] = {0.f, 0.f, 0.f, 0.f};
            float C1a[4] = {0.f, 0.f, 0.f, 0.f};
            float C1b[4] = {0.f, 0.f, 0.f, 0.f};
            #pragma unroll
            for (int kt = 0; kt < 8; kt += 2) {
                unsigned long long ba  = hb64[grp * 68 + kt * 8 + q];
                unsigned long long bbv = hb64[grp * 68 + (kt + 1) * 8 + q];
                uint32_t a0 = (uint32_t)ba,  a1 = (uint32_t)(ba >> 32);
                uint32_t c0 = (uint32_t)bbv, c1 = (uint32_t)(bbv >> 32);
                mma16816h(C0a, whi0[kt][0],   whi0[kt][1],   whi0[kt][2],   whi0[kt][3],   a0, a1);
                mma16816h(C0b, whi0[kt+1][0], whi0[kt+1][1], whi0[kt+1][2], whi0[kt+1][3], c0, c1);
                mma16816h(C1a, whi1[kt][0],   whi1[kt][1],   whi1[kt][2],   whi1[kt][3],   a0, a1);
                mma16816h(C1b, whi1[kt+1][0], whi1[kt+1][1], whi1[kt+1][2], whi1[kt+1][3], c0, c1);
            }
            ghs[(2 * q)     * 388 + m0 + grp]          = C0a[0] + C0b[0];
            ghs[(2 * q + 1) * 388 + m0 + grp]          = C0a[1] + C0b[1];
            ghs[(2 * q)     * 388 + m0 + grp + 8]      = C0a[2] + C0b[2];
            ghs[(2 * q + 1) * 388 + m0 + grp + 8]      = C0a[3] + C0b[3];
            ghs[(2 * q)     * 388 + m0 + 16 + grp]     = C1a[0] + C1b[0];
            ghs[(2 * q + 1) * 388 + m0 + 16 + grp]     = C1a[1] + C1b[1];
            ghs[(2 * q)     * 388 + m0 + 16 + grp + 8] = C1a[2] + C1b[2];
            ghs[(2 * q + 1) * 388 + m0 + 16 + grp + 8] = C1a[3] + C1b[3];
        }
        __syncthreads();

        // ---- gates: gh = col[gb] + col[gb+4] ----
        if (is_gate) {
            const float* gA = &ghs[gb * 388];
            const float* gB = &ghs[(gb + 4) * 388];
            float2 ra = *(const float2*)(gA + j);
            float2 rb = *(const float2*)(gB + j);
            float2 za = *(const float2*)(gA + HH + j);
            float2 zb = *(const float2*)(gB + HH + j);
            float2 na = *(const float2*)(gA + 2 * HH + j);
            float2 nb = *(const float2*)(gB + 2 * HH + j);
            float r0 = sig_t(pr0 + ra.x + rb.x);
            float r1 = sig_t(pr1 + ra.y + rb.y);
            float z0 = sig_t(pz0 + za.x + zb.x);
            float z1 = sig_t(pz1 + za.y + zb.y);
            float n0 = fast_tanh(pn0 + r0 * (na.x + nb.x + bhn0));
            float n1 = fast_tanh(pn1 + r1 * (na.y + nb.y + bhn1));
            hj  = fmaf(z0, hj - n0, n0);
            hj1 = fmaf(z1, hj1 - n1, n1);
            hbw[hi_word] = f16_pack(hj, hj1);
            hbw[lo_word] = f16_lo_pack(hj, hj1);
            cr = nr; cz = nz; cn = nn;
        }
        __syncthreads();
    }

    if (is_gate) {
        *(float2*)(out + (size_t)(b0 + gb) * HH + j) = make_float2(hj, hj1);
    }
}

// ================= launch =================
extern "C" void kernel_launch(void* const* d_in, const int* in_sizes, int n_in,
                              void* d_out, int out_size)
{
    const float* x    = (const float*)d_in[0];
    const float* W_ih = (const float*)d_in[1];
    const float* W_hh = (const float*)d_in[2];
    const float* b_ih = (const float*)d_in[3];
    const float* b_hh = (const float*)d_in[4];
    float* out = (float*)d_out;

    cudaFuncSetAttribute(gx_hmma_kernel,
                         cudaFuncAttributeMaxDynamicSharedMemorySize, GX_SMEM);

    prep_kernel<<<dim3(8, BB), PREP_THREADS>>>(x);
    gx_hmma_kernel<<<dim3(16, BB), GXT, GX_SMEM>>>(W_ih);
    gru_hmma_kernel<<<BB / 4, GRUT>>>(W_hh, b_ih, b_hh, out);
}